// round 7
// baseline (speedup 1.0000x reference)
#include <cuda_runtime.h>
#include <math.h>

#define BB   128
#define TT   1024
#define DD   128
#define HH   512
#define NHID 1024
#define GRID 128
#define NTHR 512
#define NGRP 4

typedef unsigned long long ull;

// dynamic smem layout: per group 6144 floats:
//   [A0:1024][A1:1024][W0:2048][W1:2048]   (A: 32k x 32row, W: 32k x 64col)
#define A_BUF 1024
#define W_BUF 2048
#define GRP_F (2 * A_BUF + 2 * W_BUF)
#define DYN_F (NGRP * GRP_F)
#define DYN_BYTES (DYN_F * 4)

// ---------------- scratch (static device memory; no allocations) -------------
__device__ float g_h[2][BB * HH];
__device__ float g_c[BB * HH];
__device__ float g_z[BB * HH];
__device__ float g_k[4][BB * HH];
__device__ float g_t1[BB * NHID];
__device__ float g_t2[BB * NHID];
__device__ float g_pred[BB * 5 * HH];
__device__ float g_dec1[BB * 5 * NHID];

__device__ unsigned g_cnt = 0;
__device__ volatile unsigned g_gen = 0;

// ---------------- grid-wide barrier ------------------------------------------
__device__ __forceinline__ void gsync() {
    __threadfence();
    __syncthreads();
    if (threadIdx.x == 0) {
        unsigned gen = g_gen;
        if (atomicAdd(&g_cnt, 1u) == GRID - 1) {
            g_cnt = 0;
            __threadfence();
            g_gen = gen + 1;
        } else {
            while (g_gen == gen) { }
        }
    }
    __syncthreads();
    __threadfence();
}

// ---------------- packed f32x2 helpers ----------------------------------------
__device__ __forceinline__ void fma2(ull& acc, ull a, ull b) {
    asm("fma.rn.f32x2 %0, %1, %2, %0;" : "+l"(acc) : "l"(a), "l"(b));
}
__device__ __forceinline__ ull addf2(ull a, ull b) {
    ull r; asm("add.rn.f32x2 %0, %1, %2;" : "=l"(r) : "l"(a), "l"(b)); return r;
}
__device__ __forceinline__ ull pack2(float x) {
    ull r; asm("mov.b64 %0, {%1, %1};" : "=l"(r) : "f"(x)); return r;
}
__device__ __forceinline__ float2 unpack2(ull v) {
    float2 r; asm("mov.b64 {%0, %1}, %2;" : "=f"(r.x), "=f"(r.y) : "l"(v)); return r;
}
__device__ __forceinline__ float sigmoidf_(float x) { return 1.f / (1.f + expf(-x)); }
__device__ __forceinline__ float eluf_(float x)     { return x > 0.f ? x : expm1f(x); }

// named barrier per 128-thread group (ids 1..4; 0 is __syncthreads)
__device__ __forceinline__ void gbar(int grp) {
    asm volatile("bar.sync %0, 128;" :: "r"(grp + 1) : "memory");
}

// ---------------- tile store helpers ------------------------------------------
// A store: transpose [row][4k] reg -> smem A[k][row]
__device__ __forceinline__ void stA(float* Ab, float4 v, int kq, int r) {
    Ab[(kq * 4 + 0) * 32 + r] = v.x;
    Ab[(kq * 4 + 1) * 32 + r] = v.y;
    Ab[(kq * 4 + 2) * 32 + r] = v.z;
    Ab[(kq * 4 + 3) * 32 + r] = v.w;
}
__device__ __forceinline__ void stW(float* Wb, float4 v, int kq, int c) {
    Wb[(kq * 4 + 0) * 64 + c] = v.x;
    Wb[(kq * 4 + 1) * 64 + c] = v.y;
    Wb[(kq * 4 + 2) * 64 + c] = v.z;
    Wb[(kq * 4 + 3) * 64 + c] = v.w;
}

// ---------------- 32-k compute: acc[r*2+p] = col-pair p of row r ---------------
__device__ __forceinline__ void kfma32(const float* Ab, const float* Wb,
                                       int tx, int ty, ull* acc) {
#pragma unroll
    for (int k = 0; k < 32; k++) {
        float4 a = *(const float4*)&Ab[k * 32 + 4 * ty];
        ulonglong2 w = *(const ulonglong2*)&Wb[k * 64 + 4 * tx];
        ull ax = pack2(a.x), ay = pack2(a.y), az = pack2(a.z), aw = pack2(a.w);
        fma2(acc[0], ax, w.x); fma2(acc[1], ax, w.y);
        fma2(acc[2], ay, w.x); fma2(acc[3], ay, w.y);
        fma2(acc[4], az, w.x); fma2(acc[5], az, w.y);
        fma2(acc[6], aw, w.x); fma2(acc[7], aw, w.y);
    }
}

// ---------------- split-K reduction + helpers ----------------------------------
// groups 1..3 dump 8 ull partials each into their own (now-free) tile area,
// layout [i][ltid] to stay bank-friendly; group 0 accumulates.
__device__ __forceinline__ void red_write(float* dyn, int grp, int ltid, ull* acc) {
    ull* rg = (ull*)(dyn + grp * GRP_F);
#pragma unroll
    for (int i = 0; i < 8; i++) rg[i * 128 + ltid] = acc[i];
}
__device__ __forceinline__ void red_accum(float* dyn, int ltid, ull* acc) {
#pragma unroll
    for (int g = 1; g < NGRP; g++) {
        ull* rg = (ull*)(dyn + g * GRP_F);
#pragma unroll
        for (int i = 0; i < 8; i++) acc[i] = addf2(acc[i], rg[i * 128 + ltid]);
    }
}

// ---------------- generic GEMM: C[M,N] = act(Aeff @ W[N,K]^T + bias) -----------
// BM=32, BN=64, split-K x4, thread tile 4x4, double-buffered, 1 bar/kblock.
template <int ACT, bool HASA2>
__device__ void gemm4(float* dyn, const float* __restrict__ A,
                      const float* __restrict__ A2, float alpha,
                      const float* __restrict__ W, const float* __restrict__ bias,
                      float* __restrict__ C, int M, int N, int K)
{
    int tid = threadIdx.x;
    int grp = tid >> 7, ltid = tid & 127;
    int tx = ltid & 15, ty = ltid >> 4;
    int lr = ltid >> 3, lkq = ltid & 7;
    float* gd = dyn + grp * GRP_F;
    int kgrp = K >> 2;
    int nkb = kgrp >> 5;
    int koff0 = grp * kgrp + lkq * 4;
    int ntiles = N >> 6;
    int total = ntiles * (M >> 5);

    for (int tile = blockIdx.x; tile < total; tile += GRID) {
        int n0 = (tile % ntiles) << 6;
        int m0 = (tile / ntiles) << 5;

        ull acc[8];
#pragma unroll
        for (int i = 0; i < 8; i++) acc[i] = 0;

        float4 av[2], wv[4];
        // prefetch kb 0
#pragma unroll
        for (int j = 0; j < 2; j++) {
            const float* p = A + (size_t)(m0 + lr + 16 * j) * K + koff0;
            float4 v = *(const float4*)p;
            if (HASA2) {
                const float* p2 = A2 + (size_t)(m0 + lr + 16 * j) * K + koff0;
                float4 v2 = *(const float4*)p2;
                v.x = fmaf(alpha, v2.x, v.x); v.y = fmaf(alpha, v2.y, v.y);
                v.z = fmaf(alpha, v2.z, v.z); v.w = fmaf(alpha, v2.w, v.w);
            }
            av[j] = v;
        }
#pragma unroll
        for (int j = 0; j < 4; j++)
            wv[j] = *(const float4*)(W + (size_t)(n0 + lr + 16 * j) * K + koff0);

        for (int kb = 0; kb < nkb; kb++) {
            float* Ab = gd + (kb & 1) * A_BUF;
            float* Wb = gd + 2 * A_BUF + (kb & 1) * W_BUF;
#pragma unroll
            for (int j = 0; j < 2; j++) stA(Ab, av[j], lkq, lr + 16 * j);
#pragma unroll
            for (int j = 0; j < 4; j++) stW(Wb, wv[j], lkq, lr + 16 * j);
            gbar(grp);
            if (kb + 1 < nkb) {
                int ko = koff0 + (kb + 1) * 32;
#pragma unroll
                for (int j = 0; j < 2; j++) {
                    const float* p = A + (size_t)(m0 + lr + 16 * j) * K + ko;
                    float4 v = *(const float4*)p;
                    if (HASA2) {
                        const float* p2 = A2 + (size_t)(m0 + lr + 16 * j) * K + ko;
                        float4 v2 = *(const float4*)p2;
                        v.x = fmaf(alpha, v2.x, v.x); v.y = fmaf(alpha, v2.y, v.y);
                        v.z = fmaf(alpha, v2.z, v.z); v.w = fmaf(alpha, v2.w, v.w);
                    }
                    av[j] = v;
                }
#pragma unroll
                for (int j = 0; j < 4; j++)
                    wv[j] = *(const float4*)(W + (size_t)(n0 + lr + 16 * j) * K + ko);
            }
            kfma32(Ab, Wb, tx, ty, acc);
        }

        __syncthreads();
        if (grp > 0) red_write(dyn, grp, ltid, acc);
        __syncthreads();
        if (grp == 0) {
            red_accum(dyn, ltid, acc);
            float4 bv = *(const float4*)(bias + n0 + 4 * tx);
#pragma unroll
            for (int r = 0; r < 4; r++) {
                float2 lo = unpack2(acc[r * 2]), hi = unpack2(acc[r * 2 + 1]);
                float4 o = make_float4(lo.x + bv.x, lo.y + bv.y, hi.x + bv.z, hi.y + bv.w);
                if (ACT == 1) {
                    o.x = eluf_(o.x); o.y = eluf_(o.y);
                    o.z = eluf_(o.z); o.w = eluf_(o.w);
                }
                if (ACT == 2) {
                    o.x = fmaxf(o.x, 0.f); o.y = fmaxf(o.y, 0.f);
                    o.z = fmaxf(o.z, 0.f); o.w = fmaxf(o.w, 0.f);
                }
                *(float4*)(C + (size_t)(m0 + 4 * ty + r) * N + n0 + 4 * tx) = o;
            }
        }
        __syncthreads();
    }
}

// ---------------- fused LSTM step ------------------------------------------------
// tile: 32 batch rows x 64 gate-cols (16 hidden units x 4 gates), 128 tiles.
// virtual K = 640 (x:0..127, h:128..639), split-K x4 -> 160 per group (5 kblocks).
__device__ void lstm4(float* dyn, float (*Gs)[64],
                      const float* __restrict__ x, const float* __restrict__ Wih,
                      const float* __restrict__ Whh, const float* __restrict__ bih,
                      const float* __restrict__ bhh, const float* __restrict__ hin,
                      float* __restrict__ hout, int t)
{
    int tid = threadIdx.x;
    int grp = tid >> 7, ltid = tid & 127;
    int tx = ltid & 15, ty = ltid >> 4;
    int lr = ltid >> 3, lkq = ltid & 7;
    float* gd = dyn + grp * GRP_F;
    int h0 = (blockIdx.x & 31) * 16;
    int m0 = (blockIdx.x >> 5) * 32;

    ull acc[8];
#pragma unroll
    for (int i = 0; i < 8; i++) acc[i] = 0;

    float4 av[2], wv[4];
    // loader for virtual k-block kb (0..4): vk0 = grp*160 + kb*32
    auto load = [&](int kb) {
        int vk0 = grp * 160 + kb * 32;
        int isx = vk0 < DD;
        int kp = (isx ? vk0 : vk0 - DD) + lkq * 4;
#pragma unroll
        for (int j = 0; j < 2; j++) {
            int m = m0 + lr + 16 * j;
            const float* p = isx ? (x + ((size_t)m * TT + t) * DD + kp)
                                 : (hin + (size_t)m * HH + kp);
            av[j] = *(const float4*)p;
        }
#pragma unroll
        for (int j = 0; j < 4; j++) {
            int c = lr + 16 * j;
            int wcol = (c >> 4) * HH + h0 + (c & 15);
            const float* p = isx ? (Wih + (size_t)wcol * DD + kp)
                                 : (Whh + (size_t)wcol * HH + kp);
            wv[j] = *(const float4*)p;
        }
    };

    load(0);
    for (int kb = 0; kb < 5; kb++) {
        float* Ab = gd + (kb & 1) * A_BUF;
        float* Wb = gd + 2 * A_BUF + (kb & 1) * W_BUF;
#pragma unroll
        for (int j = 0; j < 2; j++) stA(Ab, av[j], lkq, lr + 16 * j);
#pragma unroll
        for (int j = 0; j < 4; j++) stW(Wb, wv[j], lkq, lr + 16 * j);
        gbar(grp);
        if (kb + 1 < 5) load(kb + 1);
        kfma32(Ab, Wb, tx, ty, acc);
    }

    __syncthreads();
    if (grp > 0) red_write(dyn, grp, ltid, acc);
    __syncthreads();
    if (grp == 0) {
        red_accum(dyn, ltid, acc);
        int bcol = ((4 * tx) >> 4) * HH + h0 + ((4 * tx) & 15);
        float4 bi = *(const float4*)(bih + bcol);
        float4 bh = *(const float4*)(bhh + bcol);
#pragma unroll
        for (int r = 0; r < 4; r++) {
            float2 lo = unpack2(acc[r * 2]), hi = unpack2(acc[r * 2 + 1]);
            float4 o = make_float4(lo.x + bi.x + bh.x, lo.y + bi.y + bh.y,
                                   hi.x + bi.z + bh.z, hi.y + bi.w + bh.w);
            *(float4*)&Gs[4 * ty + r][4 * tx] = o;
        }
    }
    __syncthreads();

    // elementwise c/h update: 512 elems, 1 per thread
    int rr = tid >> 4, jj = tid & 15;
    float iv = sigmoidf_(Gs[rr][jj]);
    float fv = sigmoidf_(Gs[rr][16 + jj]);
    float gv = tanhf(Gs[rr][32 + jj]);
    float ov = sigmoidf_(Gs[rr][48 + jj]);
    int idx = (m0 + rr) * HH + h0 + jj;
    float cn = fv * g_c[idx] + iv * gv;
    g_c[idx] = cn;
    hout[idx] = ov * tanhf(cn);
    __syncthreads();
}

// ---------------- mega persistent kernel (single graph node) --------------------
__global__ __launch_bounds__(NTHR, 1) void mega_kernel(
    const float* __restrict__ x,
    const float* __restrict__ Wih, const float* __restrict__ Whh,
    const float* __restrict__ bih, const float* __restrict__ bhh,
    const float* __restrict__ ow1, const float* __restrict__ ob1,
    const float* __restrict__ ow2, const float* __restrict__ ob2,
    const float* __restrict__ ow3, const float* __restrict__ ob3,
    const float* __restrict__ dw1, const float* __restrict__ db1,
    const float* __restrict__ dw2, const float* __restrict__ db2,
    float* __restrict__ out)
{
    extern __shared__ float dyn[];
    __shared__ float Gs[32][64];

    int tid = threadIdx.x;
    int gidx = blockIdx.x * NTHR + tid;   // 65536 threads == BB*HH

    g_h[0][gidx] = 0.f;
    g_c[gidx] = 0.f;
    gsync();

    // ---- LSTM encoder: 1024 steps ----
    for (int t = 0; t < TT; t++) {
        const float* hin = (t & 1) ? g_h[1] : g_h[0];
        float* hout      = (t & 1) ? g_h[0] : g_h[1];
        lstm4(dyn, Gs, x, Wih, Whh, bih, bhh, hin, hout, t);
        gsync();
    }

    // ---- z0 = c_n; pred slot 0 ----
    {
        float v = g_c[gidx];
        g_z[gidx] = v;
        int bb = gidx >> 9, hh = gidx & 511;
        g_pred[(bb * 5) * HH + hh] = v;
    }
    gsync();

    // ---- latent ODE: 32 RK4 substeps ----
    const double dtd = (5.0 / 60.0) / 8.0;
    const float dtf  = (float)dtd;
    const float half = (float)(0.5 * dtd);
    const float dt6  = (float)(dtd / 6.0);

    for (int step = 0; step < 32; step++) {
        gemm4<1, false>(dyn, g_z, nullptr, 0.f, ow1, ob1, g_t1, BB, NHID, HH); gsync();
        gemm4<1, false>(dyn, g_t1, nullptr, 0.f, ow2, ob2, g_t2, BB, NHID, NHID); gsync();
        gemm4<0, false>(dyn, g_t2, nullptr, 0.f, ow3, ob3, g_k[0], BB, HH, NHID); gsync();

        gemm4<1, true>(dyn, g_z, g_k[0], half, ow1, ob1, g_t1, BB, NHID, HH); gsync();
        gemm4<1, false>(dyn, g_t1, nullptr, 0.f, ow2, ob2, g_t2, BB, NHID, NHID); gsync();
        gemm4<0, false>(dyn, g_t2, nullptr, 0.f, ow3, ob3, g_k[1], BB, HH, NHID); gsync();

        gemm4<1, true>(dyn, g_z, g_k[1], half, ow1, ob1, g_t1, BB, NHID, HH); gsync();
        gemm4<1, false>(dyn, g_t1, nullptr, 0.f, ow2, ob2, g_t2, BB, NHID, NHID); gsync();
        gemm4<0, false>(dyn, g_t2, nullptr, 0.f, ow3, ob3, g_k[2], BB, HH, NHID); gsync();

        gemm4<1, true>(dyn, g_z, g_k[2], dtf, ow1, ob1, g_t1, BB, NHID, HH); gsync();
        gemm4<1, false>(dyn, g_t1, nullptr, 0.f, ow2, ob2, g_t2, BB, NHID, NHID); gsync();
        gemm4<0, false>(dyn, g_t2, nullptr, 0.f, ow3, ob3, g_k[3], BB, HH, NHID); gsync();

        {
            float z = g_z[gidx] + dt6 * (g_k[0][gidx] + 2.f * (g_k[1][gidx] + g_k[2][gidx]) + g_k[3][gidx]);
            g_z[gidx] = z;
            if ((step & 7) == 7) {
                int bb = gidx >> 9, hh = gidx & 511;
                g_pred[(bb * 5 + (step >> 3) + 1) * HH + hh] = z;
            }
        }
        gsync();
    }

    // ---- decoder ----
    gemm4<2, false>(dyn, g_pred, nullptr, 0.f, dw1, db1, g_dec1, BB * 5, NHID, HH);
    gsync();
    gemm4<0, false>(dyn, g_dec1, nullptr, 0.f, dw2, db2, out, BB * 5, DD, NHID);
}

// ---------------- host side -------------------------------------------------------
extern "C" void kernel_launch(void* const* d_in, const int* in_sizes, int n_in,
                              void* d_out, int out_size)
{
    const float* inputs = (const float*)d_in[0];

    // Locate W_ih robustly: 4*512*128 elems followed by 4*512*512.
    int p = 2;
    for (int i = 1; i + 1 < n_in; i++) {
        if (in_sizes[i] == 4 * HH * DD && in_sizes[i + 1] == 4 * HH * HH) { p = i; break; }
    }
    const float* W_ih = (const float*)d_in[p + 0];
    const float* W_hh = (const float*)d_in[p + 1];
    const float* b_ih = (const float*)d_in[p + 2];
    const float* b_hh = (const float*)d_in[p + 3];
    const float* ow1 = (const float*)d_in[p + 4];
    const float* ob1 = (const float*)d_in[p + 5];
    const float* ow2 = (const float*)d_in[p + 6];
    const float* ob2 = (const float*)d_in[p + 7];
    const float* ow3 = (const float*)d_in[p + 8];
    const float* ob3 = (const float*)d_in[p + 9];
    const float* dw1 = (const float*)d_in[p + 10];
    const float* db1 = (const float*)d_in[p + 11];
    const float* dw2 = (const float*)d_in[p + 12];
    const float* db2 = (const float*)d_in[p + 13];

    static int attr_set = 0;
    cudaFuncSetAttribute(mega_kernel, cudaFuncAttributeMaxDynamicSharedMemorySize,
                         DYN_BYTES);
    (void)attr_set;

    mega_kernel<<<GRID, NTHR, DYN_BYTES>>>(inputs, W_ih, W_hh, b_ih, b_hh,
                                           ow1, ob1, ow2, ob2, ow3, ob3,
                                           dw1, db1, dw2, db2, (float*)d_out);
}

// round 8
// speedup vs baseline: 1.0027x; 1.0027x over previous
#include <cuda_runtime.h>
#include <math.h>

#define BB   128
#define TT   1024
#define DD   128
#define HH   512
#define NHID 1024
#define GRID 128
#define NTHR 512
#define NGRP 4

typedef unsigned long long ull;

// dynamic smem layout: per group 6144 floats:
//   [A0:1024][A1:1024][W0:2048][W1:2048]   (A: 32k x 32row, W: 32k x 64col)
#define A_BUF 1024
#define W_BUF 2048
#define GRP_F (2 * A_BUF + 2 * W_BUF)
#define DYN_F (NGRP * GRP_F)
#define DYN_BYTES (DYN_F * 4)

// ---------------- scratch (static device memory; no allocations) -------------
__device__ float g_h[2][BB * HH];
__device__ float g_c[BB * HH];
__device__ float g_z[BB * HH];
__device__ float g_k[4][BB * HH];
__device__ float g_t1[BB * NHID];
__device__ float g_t2[BB * NHID];
__device__ float g_pred[BB * 5 * HH];
__device__ float g_dec1[BB * 5 * NHID];

__device__ unsigned g_cnt = 0;
__device__ volatile unsigned g_gen = 0;

// ---------------- grid-wide barrier ------------------------------------------
__device__ __forceinline__ void gsync() {
    __threadfence();
    __syncthreads();
    if (threadIdx.x == 0) {
        unsigned gen = g_gen;
        if (atomicAdd(&g_cnt, 1u) == GRID - 1) {
            g_cnt = 0;
            __threadfence();
            g_gen = gen + 1;
        } else {
            while (g_gen == gen) { }
        }
    }
    __syncthreads();
    __threadfence();
}

// ---------------- packed f32x2 helpers ----------------------------------------
__device__ __forceinline__ void fma2(ull& acc, ull a, ull b) {
    asm("fma.rn.f32x2 %0, %1, %2, %0;" : "+l"(acc) : "l"(a), "l"(b));
}
__device__ __forceinline__ ull addf2(ull a, ull b) {
    ull r; asm("add.rn.f32x2 %0, %1, %2;" : "=l"(r) : "l"(a), "l"(b)); return r;
}
__device__ __forceinline__ ull pack2(float x) {
    ull r; asm("mov.b64 %0, {%1, %1};" : "=l"(r) : "f"(x)); return r;
}
__device__ __forceinline__ float2 unpack2(ull v) {
    float2 r; asm("mov.b64 {%0, %1}, %2;" : "=f"(r.x), "=f"(r.y) : "l"(v)); return r;
}
__device__ __forceinline__ float sigmoidf_(float x) { return 1.f / (1.f + expf(-x)); }
__device__ __forceinline__ float eluf_(float x)     { return x > 0.f ? x : expm1f(x); }

// named barrier per 128-thread group (ids 1..4; 0 is __syncthreads)
__device__ __forceinline__ void gbar(int grp) {
    asm volatile("bar.sync %0, 128;" :: "r"(grp + 1) : "memory");
}

// ---------------- tile store helpers ------------------------------------------
// A store: transpose [row][4k] reg -> smem A[k][row]
__device__ __forceinline__ void stA(float* Ab, float4 v, int kq, int r) {
    Ab[(kq * 4 + 0) * 32 + r] = v.x;
    Ab[(kq * 4 + 1) * 32 + r] = v.y;
    Ab[(kq * 4 + 2) * 32 + r] = v.z;
    Ab[(kq * 4 + 3) * 32 + r] = v.w;
}
__device__ __forceinline__ void stW(float* Wb, float4 v, int kq, int c) {
    Wb[(kq * 4 + 0) * 64 + c] = v.x;
    Wb[(kq * 4 + 1) * 64 + c] = v.y;
    Wb[(kq * 4 + 2) * 64 + c] = v.z;
    Wb[(kq * 4 + 3) * 64 + c] = v.w;
}

// ---------------- 32-k compute: acc[r*2+p] = col-pair p of row r ---------------
__device__ __forceinline__ void kfma32(const float* Ab, const float* Wb,
                                       int tx, int ty, ull* acc) {
#pragma unroll
    for (int k = 0; k < 32; k++) {
        float4 a = *(const float4*)&Ab[k * 32 + 4 * ty];
        ulonglong2 w = *(const ulonglong2*)&Wb[k * 64 + 4 * tx];
        ull ax = pack2(a.x), ay = pack2(a.y), az = pack2(a.z), aw = pack2(a.w);
        fma2(acc[0], ax, w.x); fma2(acc[1], ax, w.y);
        fma2(acc[2], ay, w.x); fma2(acc[3], ay, w.y);
        fma2(acc[4], az, w.x); fma2(acc[5], az, w.y);
        fma2(acc[6], aw, w.x); fma2(acc[7], aw, w.y);
    }
}

// ---------------- split-K reduction + helpers ----------------------------------
// groups 1..3 dump 8 ull partials each into their own (now-free) tile area,
// layout [i][ltid] to stay bank-friendly; group 0 accumulates.
__device__ __forceinline__ void red_write(float* dyn, int grp, int ltid, ull* acc) {
    ull* rg = (ull*)(dyn + grp * GRP_F);
#pragma unroll
    for (int i = 0; i < 8; i++) rg[i * 128 + ltid] = acc[i];
}
__device__ __forceinline__ void red_accum(float* dyn, int ltid, ull* acc) {
#pragma unroll
    for (int g = 1; g < NGRP; g++) {
        ull* rg = (ull*)(dyn + g * GRP_F);
#pragma unroll
        for (int i = 0; i < 8; i++) acc[i] = addf2(acc[i], rg[i * 128 + ltid]);
    }
}

// ---------------- generic GEMM: C[M,N] = act(Aeff @ W[N,K]^T + bias) -----------
// BM=32, BN=64, split-K x4, thread tile 4x4, double-buffered, 1 bar/kblock.
template <int ACT, bool HASA2>
__device__ void gemm4(float* dyn, const float* __restrict__ A,
                      const float* __restrict__ A2, float alpha,
                      const float* __restrict__ W, const float* __restrict__ bias,
                      float* __restrict__ C, int M, int N, int K)
{
    int tid = threadIdx.x;
    int grp = tid >> 7, ltid = tid & 127;
    int tx = ltid & 15, ty = ltid >> 4;
    int lr = ltid >> 3, lkq = ltid & 7;
    float* gd = dyn + grp * GRP_F;
    int kgrp = K >> 2;
    int nkb = kgrp >> 5;
    int koff0 = grp * kgrp + lkq * 4;
    int ntiles = N >> 6;
    int total = ntiles * (M >> 5);

    for (int tile = blockIdx.x; tile < total; tile += GRID) {
        int n0 = (tile % ntiles) << 6;
        int m0 = (tile / ntiles) << 5;

        ull acc[8];
#pragma unroll
        for (int i = 0; i < 8; i++) acc[i] = 0;

        float4 av[2], wv[4];
        // prefetch kb 0
#pragma unroll
        for (int j = 0; j < 2; j++) {
            const float* p = A + (size_t)(m0 + lr + 16 * j) * K + koff0;
            float4 v = *(const float4*)p;
            if (HASA2) {
                const float* p2 = A2 + (size_t)(m0 + lr + 16 * j) * K + koff0;
                float4 v2 = *(const float4*)p2;
                v.x = fmaf(alpha, v2.x, v.x); v.y = fmaf(alpha, v2.y, v.y);
                v.z = fmaf(alpha, v2.z, v.z); v.w = fmaf(alpha, v2.w, v.w);
            }
            av[j] = v;
        }
#pragma unroll
        for (int j = 0; j < 4; j++)
            wv[j] = *(const float4*)(W + (size_t)(n0 + lr + 16 * j) * K + koff0);

        for (int kb = 0; kb < nkb; kb++) {
            float* Ab = gd + (kb & 1) * A_BUF;
            float* Wb = gd + 2 * A_BUF + (kb & 1) * W_BUF;
#pragma unroll
            for (int j = 0; j < 2; j++) stA(Ab, av[j], lkq, lr + 16 * j);
#pragma unroll
            for (int j = 0; j < 4; j++) stW(Wb, wv[j], lkq, lr + 16 * j);
            gbar(grp);
            if (kb + 1 < nkb) {
                int ko = koff0 + (kb + 1) * 32;
#pragma unroll
                for (int j = 0; j < 2; j++) {
                    const float* p = A + (size_t)(m0 + lr + 16 * j) * K + ko;
                    float4 v = *(const float4*)p;
                    if (HASA2) {
                        const float* p2 = A2 + (size_t)(m0 + lr + 16 * j) * K + ko;
                        float4 v2 = *(const float4*)p2;
                        v.x = fmaf(alpha, v2.x, v.x); v.y = fmaf(alpha, v2.y, v.y);
                        v.z = fmaf(alpha, v2.z, v.z); v.w = fmaf(alpha, v2.w, v.w);
                    }
                    av[j] = v;
                }
#pragma unroll
                for (int j = 0; j < 4; j++)
                    wv[j] = *(const float4*)(W + (size_t)(n0 + lr + 16 * j) * K + ko);
            }
            kfma32(Ab, Wb, tx, ty, acc);
        }

        __syncthreads();
        if (grp > 0) red_write(dyn, grp, ltid, acc);
        __syncthreads();
        if (grp == 0) {
            red_accum(dyn, ltid, acc);
            float4 bv = *(const float4*)(bias + n0 + 4 * tx);
#pragma unroll
            for (int r = 0; r < 4; r++) {
                float2 lo = unpack2(acc[r * 2]), hi = unpack2(acc[r * 2 + 1]);
                float4 o = make_float4(lo.x + bv.x, lo.y + bv.y, hi.x + bv.z, hi.y + bv.w);
                if (ACT == 1) {
                    o.x = eluf_(o.x); o.y = eluf_(o.y);
                    o.z = eluf_(o.z); o.w = eluf_(o.w);
                }
                if (ACT == 2) {
                    o.x = fmaxf(o.x, 0.f); o.y = fmaxf(o.y, 0.f);
                    o.z = fmaxf(o.z, 0.f); o.w = fmaxf(o.w, 0.f);
                }
                *(float4*)(C + (size_t)(m0 + 4 * ty + r) * N + n0 + 4 * tx) = o;
            }
        }
        __syncthreads();
    }
}

// ---------------- fused LSTM step ------------------------------------------------
// tile: 32 batch rows x 64 gate-cols (16 hidden units x 4 gates), 128 tiles.
// virtual K = 640 (x:0..127, h:128..639), split-K x4 -> 160 per group (5 kblocks).
__device__ void lstm4(float* dyn, float (*Gs)[64],
                      const float* __restrict__ x, const float* __restrict__ Wih,
                      const float* __restrict__ Whh, const float* __restrict__ bih,
                      const float* __restrict__ bhh, const float* __restrict__ hin,
                      float* __restrict__ hout, int t)
{
    int tid = threadIdx.x;
    int grp = tid >> 7, ltid = tid & 127;
    int tx = ltid & 15, ty = ltid >> 4;
    int lr = ltid >> 3, lkq = ltid & 7;
    float* gd = dyn + grp * GRP_F;
    int h0 = (blockIdx.x & 31) * 16;
    int m0 = (blockIdx.x >> 5) * 32;

    ull acc[8];
#pragma unroll
    for (int i = 0; i < 8; i++) acc[i] = 0;

    float4 av[2], wv[4];
    // loader for virtual k-block kb (0..4): vk0 = grp*160 + kb*32
    auto load = [&](int kb) {
        int vk0 = grp * 160 + kb * 32;
        int isx = vk0 < DD;
        int kp = (isx ? vk0 : vk0 - DD) + lkq * 4;
#pragma unroll
        for (int j = 0; j < 2; j++) {
            int m = m0 + lr + 16 * j;
            const float* p = isx ? (x + ((size_t)m * TT + t) * DD + kp)
                                 : (hin + (size_t)m * HH + kp);
            av[j] = *(const float4*)p;
        }
#pragma unroll
        for (int j = 0; j < 4; j++) {
            int c = lr + 16 * j;
            int wcol = (c >> 4) * HH + h0 + (c & 15);
            const float* p = isx ? (Wih + (size_t)wcol * DD + kp)
                                 : (Whh + (size_t)wcol * HH + kp);
            wv[j] = *(const float4*)p;
        }
    };

    load(0);
    for (int kb = 0; kb < 5; kb++) {
        float* Ab = gd + (kb & 1) * A_BUF;
        float* Wb = gd + 2 * A_BUF + (kb & 1) * W_BUF;
#pragma unroll
        for (int j = 0; j < 2; j++) stA(Ab, av[j], lkq, lr + 16 * j);
#pragma unroll
        for (int j = 0; j < 4; j++) stW(Wb, wv[j], lkq, lr + 16 * j);
        gbar(grp);
        if (kb + 1 < 5) load(kb + 1);
        kfma32(Ab, Wb, tx, ty, acc);
    }

    __syncthreads();
    if (grp > 0) red_write(dyn, grp, ltid, acc);
    __syncthreads();
    if (grp == 0) {
        red_accum(dyn, ltid, acc);
        int bcol = ((4 * tx) >> 4) * HH + h0 + ((4 * tx) & 15);
        float4 bi = *(const float4*)(bih + bcol);
        float4 bh = *(const float4*)(bhh + bcol);
#pragma unroll
        for (int r = 0; r < 4; r++) {
            float2 lo = unpack2(acc[r * 2]), hi = unpack2(acc[r * 2 + 1]);
            float4 o = make_float4(lo.x + bi.x + bh.x, lo.y + bi.y + bh.y,
                                   hi.x + bi.z + bh.z, hi.y + bi.w + bh.w);
            *(float4*)&Gs[4 * ty + r][4 * tx] = o;
        }
    }
    __syncthreads();

    // elementwise c/h update: 512 elems, 1 per thread
    int rr = tid >> 4, jj = tid & 15;
    float iv = sigmoidf_(Gs[rr][jj]);
    float fv = sigmoidf_(Gs[rr][16 + jj]);
    float gv = tanhf(Gs[rr][32 + jj]);
    float ov = sigmoidf_(Gs[rr][48 + jj]);
    int idx = (m0 + rr) * HH + h0 + jj;
    float cn = fv * g_c[idx] + iv * gv;
    g_c[idx] = cn;
    hout[idx] = ov * tanhf(cn);
    __syncthreads();
}

// ---------------- mega persistent kernel (single graph node) --------------------
__global__ __launch_bounds__(NTHR, 1) void mega_kernel(
    const float* __restrict__ x,
    const float* __restrict__ Wih, const float* __restrict__ Whh,
    const float* __restrict__ bih, const float* __restrict__ bhh,
    const float* __restrict__ ow1, const float* __restrict__ ob1,
    const float* __restrict__ ow2, const float* __restrict__ ob2,
    const float* __restrict__ ow3, const float* __restrict__ ob3,
    const float* __restrict__ dw1, const float* __restrict__ db1,
    const float* __restrict__ dw2, const float* __restrict__ db2,
    float* __restrict__ out)
{
    extern __shared__ float dyn[];
    __shared__ float Gs[32][64];

    int tid = threadIdx.x;
    int gidx = blockIdx.x * NTHR + tid;   // 65536 threads == BB*HH

    g_h[0][gidx] = 0.f;
    g_c[gidx] = 0.f;
    gsync();

    // ---- LSTM encoder: 1024 steps ----
    for (int t = 0; t < TT; t++) {
        const float* hin = (t & 1) ? g_h[1] : g_h[0];
        float* hout      = (t & 1) ? g_h[0] : g_h[1];
        lstm4(dyn, Gs, x, Wih, Whh, bih, bhh, hin, hout, t);
        gsync();
    }

    // ---- z0 = c_n; pred slot 0 ----
    {
        float v = g_c[gidx];
        g_z[gidx] = v;
        int bb = gidx >> 9, hh = gidx & 511;
        g_pred[(bb * 5) * HH + hh] = v;
    }
    gsync();

    // ---- latent ODE: 32 RK4 substeps ----
    const double dtd = (5.0 / 60.0) / 8.0;
    const float dtf  = (float)dtd;
    const float half = (float)(0.5 * dtd);
    const float dt6  = (float)(dtd / 6.0);

    for (int step = 0; step < 32; step++) {
        gemm4<1, false>(dyn, g_z, nullptr, 0.f, ow1, ob1, g_t1, BB, NHID, HH); gsync();
        gemm4<1, false>(dyn, g_t1, nullptr, 0.f, ow2, ob2, g_t2, BB, NHID, NHID); gsync();
        gemm4<0, false>(dyn, g_t2, nullptr, 0.f, ow3, ob3, g_k[0], BB, HH, NHID); gsync();

        gemm4<1, true>(dyn, g_z, g_k[0], half, ow1, ob1, g_t1, BB, NHID, HH); gsync();
        gemm4<1, false>(dyn, g_t1, nullptr, 0.f, ow2, ob2, g_t2, BB, NHID, NHID); gsync();
        gemm4<0, false>(dyn, g_t2, nullptr, 0.f, ow3, ob3, g_k[1], BB, HH, NHID); gsync();

        gemm4<1, true>(dyn, g_z, g_k[1], half, ow1, ob1, g_t1, BB, NHID, HH); gsync();
        gemm4<1, false>(dyn, g_t1, nullptr, 0.f, ow2, ob2, g_t2, BB, NHID, NHID); gsync();
        gemm4<0, false>(dyn, g_t2, nullptr, 0.f, ow3, ob3, g_k[2], BB, HH, NHID); gsync();

        gemm4<1, true>(dyn, g_z, g_k[2], dtf, ow1, ob1, g_t1, BB, NHID, HH); gsync();
        gemm4<1, false>(dyn, g_t1, nullptr, 0.f, ow2, ob2, g_t2, BB, NHID, NHID); gsync();
        gemm4<0, false>(dyn, g_t2, nullptr, 0.f, ow3, ob3, g_k[3], BB, HH, NHID); gsync();

        {
            float z = g_z[gidx] + dt6 * (g_k[0][gidx] + 2.f * (g_k[1][gidx] + g_k[2][gidx]) + g_k[3][gidx]);
            g_z[gidx] = z;
            if ((step & 7) == 7) {
                int bb = gidx >> 9, hh = gidx & 511;
                g_pred[(bb * 5 + (step >> 3) + 1) * HH + hh] = z;
            }
        }
        gsync();
    }

    // ---- decoder ----
    gemm4<2, false>(dyn, g_pred, nullptr, 0.f, dw1, db1, g_dec1, BB * 5, NHID, HH);
    gsync();
    gemm4<0, false>(dyn, g_dec1, nullptr, 0.f, dw2, db2, out, BB * 5, DD, NHID);
}

// ---------------- host side -------------------------------------------------------
extern "C" void kernel_launch(void* const* d_in, const int* in_sizes, int n_in,
                              void* d_out, int out_size)
{
    const float* inputs = (const float*)d_in[0];

    // Locate W_ih robustly: 4*512*128 elems followed by 4*512*512.
    int p = 2;
    for (int i = 1; i + 1 < n_in; i++) {
        if (in_sizes[i] == 4 * HH * DD && in_sizes[i + 1] == 4 * HH * HH) { p = i; break; }
    }
    const float* W_ih = (const float*)d_in[p + 0];
    const float* W_hh = (const float*)d_in[p + 1];
    const float* b_ih = (const float*)d_in[p + 2];
    const float* b_hh = (const float*)d_in[p + 3];
    const float* ow1 = (const float*)d_in[p + 4];
    const float* ob1 = (const float*)d_in[p + 5];
    const float* ow2 = (const float*)d_in[p + 6];
    const float* ob2 = (const float*)d_in[p + 7];
    const float* ow3 = (const float*)d_in[p + 8];
    const float* ob3 = (const float*)d_in[p + 9];
    const float* dw1 = (const float*)d_in[p + 10];
    const float* db1 = (const float*)d_in[p + 11];
    const float* dw2 = (const float*)d_in[p + 12];
    const float* db2 = (const float*)d_in[p + 13];

    static int attr_set = 0;
    cudaFuncSetAttribute(mega_kernel, cudaFuncAttributeMaxDynamicSharedMemorySize,
                         DYN_BYTES);
    (void)attr_set;

    mega_kernel<<<GRID, NTHR, DYN_BYTES>>>(inputs, W_ih, W_hh, b_ih, b_hh,
                                           ow1, ob1, ow2, ob2, ow3, ob3,
                                           dw1, db1, dw2, db2, (float*)d_out);
}

// round 9
// speedup vs baseline: 1.5632x; 1.5589x over previous
#include <cuda_runtime.h>
#include <math.h>

#define BB   128
#define TT   1024
#define DD   128
#define HH   512
#define NHID 1024
#define GRID 128
#define NTHR 512
#define NGRP 4

typedef unsigned long long ull;

// dynamic smem layout: per group 6144 floats:
//   [A0:1024][A1:1024][W0:2048][W1:2048]   (A: 32k x 32row, W: 32k x 64col)
#define A_BUF 1024
#define W_BUF 2048
#define GRP_F (2 * A_BUF + 2 * W_BUF)
#define DYN_F (NGRP * GRP_F)
#define DYN_BYTES (DYN_F * 4)

// ---------------- scratch (static device memory; no allocations) -------------
__device__ float g_h[2][BB * HH];
__device__ float g_c[BB * HH];
__device__ float g_z[BB * HH];
__device__ float g_k[4][BB * HH];
__device__ float g_t1[BB * NHID];
__device__ float g_t2[BB * NHID];
__device__ float g_pred[BB * 5 * HH];
__device__ float g_dec1[BB * 5 * NHID];

__device__ unsigned g_cnt = 0;
__device__ volatile unsigned g_gen = 0;

// ---------------- grid-wide barrier ------------------------------------------
__device__ __forceinline__ void gsync() {
    __threadfence();
    __syncthreads();
    if (threadIdx.x == 0) {
        unsigned gen = g_gen;
        if (atomicAdd(&g_cnt, 1u) == GRID - 1) {
            g_cnt = 0;
            __threadfence();
            g_gen = gen + 1;
        } else {
            while (g_gen == gen) { }
        }
    }
    __syncthreads();
    __threadfence();
}

// ---------------- packed f32x2 helpers ----------------------------------------
__device__ __forceinline__ void fma2(ull& acc, ull a, ull b) {
    asm("fma.rn.f32x2 %0, %1, %2, %0;" : "+l"(acc) : "l"(a), "l"(b));
}
__device__ __forceinline__ ull addf2(ull a, ull b) {
    ull r; asm("add.rn.f32x2 %0, %1, %2;" : "=l"(r) : "l"(a), "l"(b)); return r;
}
__device__ __forceinline__ ull pack2(float x) {
    ull r; asm("mov.b64 %0, {%1, %1};" : "=l"(r) : "f"(x)); return r;
}
__device__ __forceinline__ float2 unpack2(ull v) {
    float2 r; asm("mov.b64 {%0, %1}, %2;" : "=f"(r.x), "=f"(r.y) : "l"(v)); return r;
}
__device__ __forceinline__ float sigmoidf_(float x) { return 1.f / (1.f + expf(-x)); }
__device__ __forceinline__ float eluf_(float x)     { return x > 0.f ? x : expm1f(x); }

// named barrier per 128-thread group (ids 1..4; 0 is __syncthreads)
__device__ __forceinline__ void gbar(int grp) {
    asm volatile("bar.sync %0, 128;" :: "r"(grp + 1) : "memory");
}

// ---------------- XOR-swizzled tile stores -------------------------------------
// local k = lkq*4 + j  ->  swizzle constant c = k>>2 = lkq (varies per lane!)
// A (32 rows): word = k*32 + ((rg ^ lkq)&7)*4 + (r&3), rg = r>>2.
// Store banks: rg fixed per instr, (rg^lkq) 8 distinct, x (r&3) -> 32 banks. CF.
__device__ __forceinline__ void stA32(float* Ab, float4 v, int lkq, int r) {
    float* p = Ab + lkq * 4 * 32 + ((((r >> 2) ^ lkq) & 7) << 2) + (r & 3);
    p[0] = v.x; p[32] = v.y; p[64] = v.z; p[96] = v.w;
}
// A (16 rows): 2-bit swizzle, c = lkq&3 (2-way store conflict, small volume)
__device__ __forceinline__ void stA16(float* Ab, float4 v, int lkq, int r) {
    float* p = Ab + lkq * 4 * 16 + ((((r >> 2) ^ lkq) & 3) << 2) + (r & 3);
    p[0] = v.x; p[16] = v.y; p[32] = v.z; p[48] = v.w;
}
// W (64 cols): word = k*64 + ((g ^ lkq (low3))&15)*4 + (c&3), g = col>>2 (4b).
__device__ __forceinline__ void stW64(float* Wb, float4 v, int lkq, int col) {
    float* p = Wb + lkq * 4 * 64 + ((((col >> 2) ^ lkq) & 15) << 2) + (col & 3);
    p[0] = v.x; p[64] = v.y; p[128] = v.z; p[192] = v.w;
}

// ---------------- swizzled k-block compute --------------------------------------
// BM=32: thread rows 4ty..4ty+3 (ty 0..7), cols 4tx..4tx+3 (tx 0..15)
__device__ __forceinline__ void kfma32(const float* Ab, const float* Wb,
                                       int tx, int ty, ull* acc) {
#pragma unroll
    for (int k = 0; k < 32; k++) {
        const int c = k >> 2;
        float4 a = *(const float4*)&Ab[k * 32 + (((ty ^ c) & 7) << 2)];
        ulonglong2 w = *(const ulonglong2*)&Wb[k * 64 + (((tx ^ c) & 15) << 2)];
        ull ax = pack2(a.x), ay = pack2(a.y), az = pack2(a.z), aw = pack2(a.w);
        fma2(acc[0], ax, w.x); fma2(acc[1], ax, w.y);
        fma2(acc[2], ay, w.x); fma2(acc[3], ay, w.y);
        fma2(acc[4], az, w.x); fma2(acc[5], az, w.y);
        fma2(acc[6], aw, w.x); fma2(acc[7], aw, w.y);
    }
}
// BM=16: thread rows 2ty, 2ty+1
__device__ __forceinline__ void kfma16(const float* Ab, const float* Wb,
                                       int tx, int ty, ull* acc) {
#pragma unroll
    for (int k = 0; k < 32; k++) {
        const int c = k >> 2;
        float2 a = *(const float2*)&Ab[k * 16 + ((((ty >> 1) ^ c) & 3) << 2) + ((ty & 1) << 1)];
        ulonglong2 w = *(const ulonglong2*)&Wb[k * 64 + (((tx ^ c) & 15) << 2)];
        ull ax = pack2(a.x), ay = pack2(a.y);
        fma2(acc[0], ax, w.x); fma2(acc[1], ax, w.y);
        fma2(acc[2], ay, w.x); fma2(acc[3], ay, w.y);
    }
}

// ---------------- split-K reduction ----------------------------------------------
template <int NACC>
__device__ __forceinline__ void red_write(float* dyn, int grp, int ltid, ull* acc) {
    ull* rg = (ull*)(dyn + grp * GRP_F);
#pragma unroll
    for (int i = 0; i < NACC; i++) rg[i * 128 + ltid] = acc[i];
}
template <int NACC>
__device__ __forceinline__ void red_accum(float* dyn, int ltid, ull* acc) {
#pragma unroll
    for (int g = 1; g < NGRP; g++) {
        ull* rg = (ull*)(dyn + g * GRP_F);
#pragma unroll
        for (int i = 0; i < NACC; i++) acc[i] = addf2(acc[i], rg[i * 128 + ltid]);
    }
}

// ---------------- generic GEMM: C[M,N] = act(Aeff @ W[N,K]^T + bias) -------------
// BN=64, BM=32 or 16, split-K x4 per block, double-buffered, swizzled tiles.
template <int ACT, bool HASA2, int BM>
__device__ void gemm_g(float* dyn, const float* __restrict__ A,
                       const float* __restrict__ A2, float alpha,
                       const float* __restrict__ W, const float* __restrict__ bias,
                       float* __restrict__ C, int M, int N, int K)
{
    constexpr int AV = BM / 16;        // float4 A loads per thread (2 or 1)
    constexpr int NACC = BM / 4;       // accumulators (8 or 4)
    constexpr int RPT = BM / 8;        // rows per thread (4 or 2)

    const int tid = threadIdx.x;
    const int grp = tid >> 7, ltid = tid & 127;
    const int tx = ltid & 15, ty = ltid >> 4;
    const int lr = ltid >> 3, lkq = ltid & 7;
    float* gd = dyn + grp * GRP_F;
    const int kgrp = K >> 2, nkb = kgrp >> 5;
    const int koff0 = grp * kgrp + lkq * 4;
    const int ntiles = N >> 6;
    const int total = ntiles * (M / BM);

    for (int tile = blockIdx.x; tile < total; tile += GRID) {
        int n0 = (tile % ntiles) << 6;
        int m0 = (tile / ntiles) * BM;

        ull acc[NACC];
#pragma unroll
        for (int i = 0; i < NACC; i++) acc[i] = 0;

        float4 av[AV], wv[4];
#pragma unroll
        for (int j = 0; j < AV; j++) {
            const float* p = A + (size_t)(m0 + lr + 16 * j) * K + koff0;
            float4 v = *(const float4*)p;
            if (HASA2) {
                float4 v2 = *(const float4*)(A2 + (size_t)(m0 + lr + 16 * j) * K + koff0);
                v.x = fmaf(alpha, v2.x, v.x); v.y = fmaf(alpha, v2.y, v.y);
                v.z = fmaf(alpha, v2.z, v.z); v.w = fmaf(alpha, v2.w, v.w);
            }
            av[j] = v;
        }
#pragma unroll
        for (int j = 0; j < 4; j++)
            wv[j] = *(const float4*)(W + (size_t)(n0 + lr + 16 * j) * K + koff0);

        for (int kb = 0; kb < nkb; kb++) {
            float* Ab = gd + (kb & 1) * A_BUF;
            float* Wb = gd + 2 * A_BUF + (kb & 1) * W_BUF;
#pragma unroll
            for (int j = 0; j < AV; j++) {
                if (BM == 32) stA32(Ab, av[j], lkq, lr + 16 * j);
                else          stA16(Ab, av[j], lkq, lr);
            }
#pragma unroll
            for (int j = 0; j < 4; j++) stW64(Wb, wv[j], lkq, lr + 16 * j);
            gbar(grp);
            if (kb + 1 < nkb) {
                int ko = koff0 + (kb + 1) * 32;
#pragma unroll
                for (int j = 0; j < AV; j++) {
                    const float* p = A + (size_t)(m0 + lr + 16 * j) * K + ko;
                    float4 v = *(const float4*)p;
                    if (HASA2) {
                        float4 v2 = *(const float4*)(A2 + (size_t)(m0 + lr + 16 * j) * K + ko);
                        v.x = fmaf(alpha, v2.x, v.x); v.y = fmaf(alpha, v2.y, v.y);
                        v.z = fmaf(alpha, v2.z, v.z); v.w = fmaf(alpha, v2.w, v.w);
                    }
                    av[j] = v;
                }
#pragma unroll
                for (int j = 0; j < 4; j++)
                    wv[j] = *(const float4*)(W + (size_t)(n0 + lr + 16 * j) * K + ko);
            }
            if (BM == 32) kfma32(Ab, Wb, tx, ty, acc);
            else          kfma16(Ab, Wb, tx, ty, acc);
        }

        __syncthreads();
        if (grp > 0) red_write<NACC>(dyn, grp, ltid, acc);
        __syncthreads();
        if (grp == 0) {
            red_accum<NACC>(dyn, ltid, acc);
            float4 bv = *(const float4*)(bias + n0 + 4 * tx);
#pragma unroll
            for (int r = 0; r < RPT; r++) {
                int row = m0 + RPT * ty + r;
                float2 lo = unpack2(acc[r * 2]), hi = unpack2(acc[r * 2 + 1]);
                float4 o = make_float4(lo.x + bv.x, lo.y + bv.y, hi.x + bv.z, hi.y + bv.w);
                if (ACT == 1) {
                    o.x = eluf_(o.x); o.y = eluf_(o.y);
                    o.z = eluf_(o.z); o.w = eluf_(o.w);
                }
                if (ACT == 2) {
                    o.x = fmaxf(o.x, 0.f); o.y = fmaxf(o.y, 0.f);
                    o.z = fmaxf(o.z, 0.f); o.w = fmaxf(o.w, 0.f);
                }
                *(float4*)(C + (size_t)row * N + n0 + 4 * tx) = o;
            }
        }
        __syncthreads();
    }
}

// ---------------- fused LSTM step ---------------------------------------------------
// tile: 32 batch rows x 64 gate-cols (16 hidden units x 4 gates), 128 tiles.
// virtual K = 640 (x:0..127, h:128..639), split-K x4 -> 160 per group (5 kblocks).
__device__ void lstm4(float* dyn, float (*Gs)[64],
                      const float* __restrict__ x, const float* __restrict__ Wih,
                      const float* __restrict__ Whh, const float* __restrict__ bih,
                      const float* __restrict__ bhh, const float* __restrict__ hin,
                      float* __restrict__ hout, int t)
{
    int tid = threadIdx.x;
    int grp = tid >> 7, ltid = tid & 127;
    int tx = ltid & 15, ty = ltid >> 4;
    int lr = ltid >> 3, lkq = ltid & 7;
    float* gd = dyn + grp * GRP_F;
    int h0 = (blockIdx.x & 31) * 16;
    int m0 = (blockIdx.x >> 5) * 32;

    ull acc[8];
#pragma unroll
    for (int i = 0; i < 8; i++) acc[i] = 0;

    float4 av[2], wv[4];
    auto load = [&](int kb) {
        int vk0 = grp * 160 + kb * 32;
        int isx = vk0 < DD;
        int kp = (isx ? vk0 : vk0 - DD) + lkq * 4;
#pragma unroll
        for (int j = 0; j < 2; j++) {
            int m = m0 + lr + 16 * j;
            const float* p = isx ? (x + ((size_t)m * TT + t) * DD + kp)
                                 : (hin + (size_t)m * HH + kp);
            av[j] = *(const float4*)p;
        }
#pragma unroll
        for (int j = 0; j < 4; j++) {
            int c = lr + 16 * j;
            int wcol = (c >> 4) * HH + h0 + (c & 15);
            const float* p = isx ? (Wih + (size_t)wcol * DD + kp)
                                 : (Whh + (size_t)wcol * HH + kp);
            wv[j] = *(const float4*)p;
        }
    };

    load(0);
    for (int kb = 0; kb < 5; kb++) {
        float* Ab = gd + (kb & 1) * A_BUF;
        float* Wb = gd + 2 * A_BUF + (kb & 1) * W_BUF;
#pragma unroll
        for (int j = 0; j < 2; j++) stA32(Ab, av[j], lkq, lr + 16 * j);
#pragma unroll
        for (int j = 0; j < 4; j++) stW64(Wb, wv[j], lkq, lr + 16 * j);
        gbar(grp);
        if (kb + 1 < 5) load(kb + 1);
        kfma32(Ab, Wb, tx, ty, acc);
    }

    __syncthreads();
    if (grp > 0) red_write<8>(dyn, grp, ltid, acc);
    __syncthreads();
    if (grp == 0) {
        red_accum<8>(dyn, ltid, acc);
        int bcol = ((4 * tx) >> 4) * HH + h0 + ((4 * tx) & 15);
        float4 bi = *(const float4*)(bih + bcol);
        float4 bh = *(const float4*)(bhh + bcol);
#pragma unroll
        for (int r = 0; r < 4; r++) {
            float2 lo = unpack2(acc[r * 2]), hi = unpack2(acc[r * 2 + 1]);
            float4 o = make_float4(lo.x + bi.x + bh.x, lo.y + bi.y + bh.y,
                                   hi.x + bi.z + bh.z, hi.y + bi.w + bh.w);
            *(float4*)&Gs[4 * ty + r][4 * tx] = o;
        }
    }
    __syncthreads();

    // elementwise c/h update: 512 elems, 1 per thread
    int rr = tid >> 4, jj = tid & 15;
    float iv = sigmoidf_(Gs[rr][jj]);
    float fv = sigmoidf_(Gs[rr][16 + jj]);
    float gv = tanhf(Gs[rr][32 + jj]);
    float ov = sigmoidf_(Gs[rr][48 + jj]);
    int idx = (m0 + rr) * HH + h0 + jj;
    float cn = fv * g_c[idx] + iv * gv;
    g_c[idx] = cn;
    hout[idx] = ov * tanhf(cn);
    __syncthreads();
}

// ---------------- mega persistent kernel (single graph node) ------------------------
__global__ __launch_bounds__(NTHR, 1) void mega_kernel(
    const float* __restrict__ x,
    const float* __restrict__ Wih, const float* __restrict__ Whh,
    const float* __restrict__ bih, const float* __restrict__ bhh,
    const float* __restrict__ ow1, const float* __restrict__ ob1,
    const float* __restrict__ ow2, const float* __restrict__ ob2,
    const float* __restrict__ ow3, const float* __restrict__ ob3,
    const float* __restrict__ dw1, const float* __restrict__ db1,
    const float* __restrict__ dw2, const float* __restrict__ db2,
    float* __restrict__ out)
{
    extern __shared__ float dyn[];
    __shared__ float Gs[32][64];

    int tid = threadIdx.x;
    int gidx = blockIdx.x * NTHR + tid;   // 65536 threads == BB*HH

    g_h[0][gidx] = 0.f;
    g_c[gidx] = 0.f;
    gsync();

    // ---- LSTM encoder: 1024 steps ----
    for (int t = 0; t < TT; t++) {
        const float* hin = (t & 1) ? g_h[1] : g_h[0];
        float* hout      = (t & 1) ? g_h[0] : g_h[1];
        lstm4(dyn, Gs, x, Wih, Whh, bih, bhh, hin, hout, t);
        gsync();
    }

    // ---- z0 = c_n; pred slot 0 ----
    {
        float v = g_c[gidx];
        g_z[gidx] = v;
        int bb = gidx >> 9, hh = gidx & 511;
        g_pred[(bb * 5) * HH + hh] = v;
    }
    gsync();

    // ---- latent ODE: 32 RK4 substeps ----
    const double dtd = (5.0 / 60.0) / 8.0;
    const float dtf  = (float)dtd;
    const float half = (float)(0.5 * dtd);
    const float dt6  = (float)(dtd / 6.0);

    for (int step = 0; step < 32; step++) {
        gemm_g<1, false, 16>(dyn, g_z, nullptr, 0.f, ow1, ob1, g_t1, BB, NHID, HH); gsync();
        gemm_g<1, false, 16>(dyn, g_t1, nullptr, 0.f, ow2, ob2, g_t2, BB, NHID, NHID); gsync();
        gemm_g<0, false, 16>(dyn, g_t2, nullptr, 0.f, ow3, ob3, g_k[0], BB, HH, NHID); gsync();

        gemm_g<1, true, 16>(dyn, g_z, g_k[0], half, ow1, ob1, g_t1, BB, NHID, HH); gsync();
        gemm_g<1, false, 16>(dyn, g_t1, nullptr, 0.f, ow2, ob2, g_t2, BB, NHID, NHID); gsync();
        gemm_g<0, false, 16>(dyn, g_t2, nullptr, 0.f, ow3, ob3, g_k[1], BB, HH, NHID); gsync();

        gemm_g<1, true, 16>(dyn, g_z, g_k[1], half, ow1, ob1, g_t1, BB, NHID, HH); gsync();
        gemm_g<1, false, 16>(dyn, g_t1, nullptr, 0.f, ow2, ob2, g_t2, BB, NHID, NHID); gsync();
        gemm_g<0, false, 16>(dyn, g_t2, nullptr, 0.f, ow3, ob3, g_k[2], BB, HH, NHID); gsync();

        gemm_g<1, true, 16>(dyn, g_z, g_k[2], dtf, ow1, ob1, g_t1, BB, NHID, HH); gsync();
        gemm_g<1, false, 16>(dyn, g_t1, nullptr, 0.f, ow2, ob2, g_t2, BB, NHID, NHID); gsync();
        gemm_g<0, false, 16>(dyn, g_t2, nullptr, 0.f, ow3, ob3, g_k[3], BB, HH, NHID); gsync();

        {
            float z = g_z[gidx] + dt6 * (g_k[0][gidx] + 2.f * (g_k[1][gidx] + g_k[2][gidx]) + g_k[3][gidx]);
            g_z[gidx] = z;
            if ((step & 7) == 7) {
                int bb = gidx >> 9, hh = gidx & 511;
                g_pred[(bb * 5 + (step >> 3) + 1) * HH + hh] = z;
            }
        }
        gsync();
    }

    // ---- decoder ----
    gemm_g<2, false, 32>(dyn, g_pred, nullptr, 0.f, dw1, db1, g_dec1, BB * 5, NHID, HH);
    gsync();
    gemm_g<0, false, 32>(dyn, g_dec1, nullptr, 0.f, dw2, db2, out, BB * 5, DD, NHID);
}

// ---------------- host side -----------------------------------------------------------
extern "C" void kernel_launch(void* const* d_in, const int* in_sizes, int n_in,
                              void* d_out, int out_size)
{
    const float* inputs = (const float*)d_in[0];

    // Locate W_ih robustly: 4*512*128 elems followed by 4*512*512.
    int p = 2;
    for (int i = 1; i + 1 < n_in; i++) {
        if (in_sizes[i] == 4 * HH * DD && in_sizes[i + 1] == 4 * HH * HH) { p = i; break; }
    }
    const float* W_ih = (const float*)d_in[p + 0];
    const float* W_hh = (const float*)d_in[p + 1];
    const float* b_ih = (const float*)d_in[p + 2];
    const float* b_hh = (const float*)d_in[p + 3];
    const float* ow1 = (const float*)d_in[p + 4];
    const float* ob1 = (const float*)d_in[p + 5];
    const float* ow2 = (const float*)d_in[p + 6];
    const float* ob2 = (const float*)d_in[p + 7];
    const float* ow3 = (const float*)d_in[p + 8];
    const float* ob3 = (const float*)d_in[p + 9];
    const float* dw1 = (const float*)d_in[p + 10];
    const float* db1 = (const float*)d_in[p + 11];
    const float* dw2 = (const float*)d_in[p + 12];
    const float* db2 = (const float*)d_in[p + 13];

    cudaFuncSetAttribute(mega_kernel, cudaFuncAttributeMaxDynamicSharedMemorySize,
                         DYN_BYTES);

    mega_kernel<<<GRID, NTHR, DYN_BYTES>>>(inputs, W_ih, W_hh, b_ih, b_hh,
                                           ow1, ob1, ow2, ob2, ow3, ob3,
                                           dw1, db1, dw2, db2, (float*)d_out);
}

// round 10
// speedup vs baseline: 1.5672x; 1.0026x over previous
#include <cuda_runtime.h>
#include <math.h>

#define BB   128
#define TT   1024
#define DD   128
#define HH   512
#define NHID 1024
#define GRID 128
#define NTHR 512
#define NGRP 4

typedef unsigned long long ull;

// dynamic smem layout: per group 6144 floats:
//   [A0:1024][A1:1024][W0:2048][W1:2048]   (A: 32k x 32row, W: 32k x 64col)
#define A_BUF 1024
#define W_BUF 2048
#define GRP_F (2 * A_BUF + 2 * W_BUF)
#define DYN_F (NGRP * GRP_F)
#define DYN_BYTES (DYN_F * 4)

// ---------------- scratch (static device memory; no allocations) -------------
__device__ float g_h[2][BB * HH];
__device__ float g_c[BB * HH];
__device__ float g_z[BB * HH];
__device__ float g_k[4][BB * HH];
__device__ float g_t1[BB * NHID];
__device__ float g_t2[BB * NHID];
__device__ float g_pred[BB * 5 * HH];
__device__ float g_dec1[BB * 5 * NHID];

__device__ unsigned g_cnt = 0;
__device__ volatile unsigned g_gen = 0;

// ---------------- grid-wide barrier ------------------------------------------
__device__ __forceinline__ void gsync() {
    __threadfence();
    __syncthreads();
    if (threadIdx.x == 0) {
        unsigned gen = g_gen;
        if (atomicAdd(&g_cnt, 1u) == GRID - 1) {
            g_cnt = 0;
            __threadfence();
            g_gen = gen + 1;
        } else {
            while (g_gen == gen) { }
        }
    }
    __syncthreads();
    __threadfence();
}

// ---------------- packed f32x2 helpers ----------------------------------------
__device__ __forceinline__ void fma2(ull& acc, ull a, ull b) {
    asm("fma.rn.f32x2 %0, %1, %2, %0;" : "+l"(acc) : "l"(a), "l"(b));
}
__device__ __forceinline__ ull addf2(ull a, ull b) {
    ull r; asm("add.rn.f32x2 %0, %1, %2;" : "=l"(r) : "l"(a), "l"(b)); return r;
}
__device__ __forceinline__ ull pack2(float x) {
    ull r; asm("mov.b64 %0, {%1, %1};" : "=l"(r) : "f"(x)); return r;
}
__device__ __forceinline__ float2 unpack2(ull v) {
    float2 r; asm("mov.b64 {%0, %1}, %2;" : "=f"(r.x), "=f"(r.y) : "l"(v)); return r;
}
__device__ __forceinline__ float sigmoidf_(float x) { return 1.f / (1.f + expf(-x)); }
__device__ __forceinline__ float eluf_(float x)     { return x > 0.f ? x : expm1f(x); }

// named barrier per 128-thread group (ids 1..4; 0 is __syncthreads)
__device__ __forceinline__ void gbar(int grp) {
    asm volatile("bar.sync %0, 128;" :: "r"(grp + 1) : "memory");
}

// ---------------- XOR-swizzled tile stores -------------------------------------
// local k = lkq*4 + j  ->  swizzle constant c = k>>2 = lkq (varies per lane!)
// A (32 rows): word = k*32 + ((rg ^ lkq)&7)*4 + (r&3), rg = r>>2.
// Store banks: rg fixed per instr, (rg^lkq) 8 distinct, x (r&3) -> 32 banks. CF.
__device__ __forceinline__ void stA32(float* Ab, float4 v, int lkq, int r) {
    float* p = Ab + lkq * 4 * 32 + ((((r >> 2) ^ lkq) & 7) << 2) + (r & 3);
    p[0] = v.x; p[32] = v.y; p[64] = v.z; p[96] = v.w;
}
// A (16 rows): 2-bit swizzle, c = lkq&3 (2-way store conflict, small volume)
__device__ __forceinline__ void stA16(float* Ab, float4 v, int lkq, int r) {
    float* p = Ab + lkq * 4 * 16 + ((((r >> 2) ^ lkq) & 3) << 2) + (r & 3);
    p[0] = v.x; p[16] = v.y; p[32] = v.z; p[48] = v.w;
}
// W (64 cols): word = k*64 + ((g ^ lkq (low3))&15)*4 + (c&3), g = col>>2 (4b).
__device__ __forceinline__ void stW64(float* Wb, float4 v, int lkq, int col) {
    float* p = Wb + lkq * 4 * 64 + ((((col >> 2) ^ lkq) & 15) << 2) + (col & 3);
    p[0] = v.x; p[64] = v.y; p[128] = v.z; p[192] = v.w;
}

// ---------------- swizzled k-block compute --------------------------------------
// BM=32: thread rows 4ty..4ty+3 (ty 0..7), cols 4tx..4tx+3 (tx 0..15)
__device__ __forceinline__ void kfma32(const float* Ab, const float* Wb,
                                       int tx, int ty, ull* acc) {
#pragma unroll
    for (int k = 0; k < 32; k++) {
        const int c = k >> 2;
        float4 a = *(const float4*)&Ab[k * 32 + (((ty ^ c) & 7) << 2)];
        ulonglong2 w = *(const ulonglong2*)&Wb[k * 64 + (((tx ^ c) & 15) << 2)];
        ull ax = pack2(a.x), ay = pack2(a.y), az = pack2(a.z), aw = pack2(a.w);
        fma2(acc[0], ax, w.x); fma2(acc[1], ax, w.y);
        fma2(acc[2], ay, w.x); fma2(acc[3], ay, w.y);
        fma2(acc[4], az, w.x); fma2(acc[5], az, w.y);
        fma2(acc[6], aw, w.x); fma2(acc[7], aw, w.y);
    }
}
// BM=16: thread rows 2ty, 2ty+1
__device__ __forceinline__ void kfma16(const float* Ab, const float* Wb,
                                       int tx, int ty, ull* acc) {
#pragma unroll
    for (int k = 0; k < 32; k++) {
        const int c = k >> 2;
        float2 a = *(const float2*)&Ab[k * 16 + ((((ty >> 1) ^ c) & 3) << 2) + ((ty & 1) << 1)];
        ulonglong2 w = *(const ulonglong2*)&Wb[k * 64 + (((tx ^ c) & 15) << 2)];
        ull ax = pack2(a.x), ay = pack2(a.y);
        fma2(acc[0], ax, w.x); fma2(acc[1], ax, w.y);
        fma2(acc[2], ay, w.x); fma2(acc[3], ay, w.y);
    }
}

// ---------------- split-K reduction ----------------------------------------------
template <int NACC>
__device__ __forceinline__ void red_write(float* dyn, int grp, int ltid, ull* acc) {
    ull* rg = (ull*)(dyn + grp * GRP_F);
#pragma unroll
    for (int i = 0; i < NACC; i++) rg[i * 128 + ltid] = acc[i];
}
template <int NACC>
__device__ __forceinline__ void red_accum(float* dyn, int ltid, ull* acc) {
#pragma unroll
    for (int g = 1; g < NGRP; g++) {
        ull* rg = (ull*)(dyn + g * GRP_F);
#pragma unroll
        for (int i = 0; i < NACC; i++) acc[i] = addf2(acc[i], rg[i * 128 + ltid]);
    }
}

// ---------------- generic GEMM: C[M,N] = act(Aeff @ W[N,K]^T + bias) -------------
// BN=64, BM=32 or 16, split-K x4 per block, double-buffered, swizzled tiles.
template <int ACT, bool HASA2, int BM>
__device__ void gemm_g(float* dyn, const float* __restrict__ A,
                       const float* __restrict__ A2, float alpha,
                       const float* __restrict__ W, const float* __restrict__ bias,
                       float* __restrict__ C, int M, int N, int K)
{
    constexpr int AV = BM / 16;        // float4 A loads per thread (2 or 1)
    constexpr int NACC = BM / 4;       // accumulators (8 or 4)
    constexpr int RPT = BM / 8;        // rows per thread (4 or 2)

    const int tid = threadIdx.x;
    const int grp = tid >> 7, ltid = tid & 127;
    const int tx = ltid & 15, ty = ltid >> 4;
    const int lr = ltid >> 3, lkq = ltid & 7;
    float* gd = dyn + grp * GRP_F;
    const int kgrp = K >> 2, nkb = kgrp >> 5;
    const int koff0 = grp * kgrp + lkq * 4;
    const int ntiles = N >> 6;
    const int total = ntiles * (M / BM);

    for (int tile = blockIdx.x; tile < total; tile += GRID) {
        int n0 = (tile % ntiles) << 6;
        int m0 = (tile / ntiles) * BM;

        ull acc[NACC];
#pragma unroll
        for (int i = 0; i < NACC; i++) acc[i] = 0;

        float4 av[AV], wv[4];
#pragma unroll
        for (int j = 0; j < AV; j++) {
            const float* p = A + (size_t)(m0 + lr + 16 * j) * K + koff0;
            float4 v = *(const float4*)p;
            if (HASA2) {
                float4 v2 = *(const float4*)(A2 + (size_t)(m0 + lr + 16 * j) * K + koff0);
                v.x = fmaf(alpha, v2.x, v.x); v.y = fmaf(alpha, v2.y, v.y);
                v.z = fmaf(alpha, v2.z, v.z); v.w = fmaf(alpha, v2.w, v.w);
            }
            av[j] = v;
        }
#pragma unroll
        for (int j = 0; j < 4; j++)
            wv[j] = *(const float4*)(W + (size_t)(n0 + lr + 16 * j) * K + koff0);

        for (int kb = 0; kb < nkb; kb++) {
            float* Ab = gd + (kb & 1) * A_BUF;
            float* Wb = gd + 2 * A_BUF + (kb & 1) * W_BUF;
#pragma unroll
            for (int j = 0; j < AV; j++) {
                if (BM == 32) stA32(Ab, av[j], lkq, lr + 16 * j);
                else          stA16(Ab, av[j], lkq, lr);
            }
#pragma unroll
            for (int j = 0; j < 4; j++) stW64(Wb, wv[j], lkq, lr + 16 * j);
            gbar(grp);
            if (kb + 1 < nkb) {
                int ko = koff0 + (kb + 1) * 32;
#pragma unroll
                for (int j = 0; j < AV; j++) {
                    const float* p = A + (size_t)(m0 + lr + 16 * j) * K + ko;
                    float4 v = *(const float4*)p;
                    if (HASA2) {
                        float4 v2 = *(const float4*)(A2 + (size_t)(m0 + lr + 16 * j) * K + ko);
                        v.x = fmaf(alpha, v2.x, v.x); v.y = fmaf(alpha, v2.y, v.y);
                        v.z = fmaf(alpha, v2.z, v.z); v.w = fmaf(alpha, v2.w, v.w);
                    }
                    av[j] = v;
                }
#pragma unroll
                for (int j = 0; j < 4; j++)
                    wv[j] = *(const float4*)(W + (size_t)(n0 + lr + 16 * j) * K + ko);
            }
            if (BM == 32) kfma32(Ab, Wb, tx, ty, acc);
            else          kfma16(Ab, Wb, tx, ty, acc);
        }

        __syncthreads();
        if (grp > 0) red_write<NACC>(dyn, grp, ltid, acc);
        __syncthreads();
        if (grp == 0) {
            red_accum<NACC>(dyn, ltid, acc);
            float4 bv = *(const float4*)(bias + n0 + 4 * tx);
#pragma unroll
            for (int r = 0; r < RPT; r++) {
                int row = m0 + RPT * ty + r;
                float2 lo = unpack2(acc[r * 2]), hi = unpack2(acc[r * 2 + 1]);
                float4 o = make_float4(lo.x + bv.x, lo.y + bv.y, hi.x + bv.z, hi.y + bv.w);
                if (ACT == 1) {
                    o.x = eluf_(o.x); o.y = eluf_(o.y);
                    o.z = eluf_(o.z); o.w = eluf_(o.w);
                }
                if (ACT == 2) {
                    o.x = fmaxf(o.x, 0.f); o.y = fmaxf(o.y, 0.f);
                    o.z = fmaxf(o.z, 0.f); o.w = fmaxf(o.w, 0.f);
                }
                *(float4*)(C + (size_t)row * N + n0 + 4 * tx) = o;
            }
        }
        __syncthreads();
    }
}

// ---------------- fused LSTM step ---------------------------------------------------
// tile: 32 batch rows x 64 gate-cols (16 hidden units x 4 gates), 128 tiles.
// virtual K = 640 (x:0..127, h:128..639), split-K x4 -> 160 per group (5 kblocks).
__device__ void lstm4(float* dyn, float (*Gs)[64],
                      const float* __restrict__ x, const float* __restrict__ Wih,
                      const float* __restrict__ Whh, const float* __restrict__ bih,
                      const float* __restrict__ bhh, const float* __restrict__ hin,
                      float* __restrict__ hout, int t)
{
    int tid = threadIdx.x;
    int grp = tid >> 7, ltid = tid & 127;
    int tx = ltid & 15, ty = ltid >> 4;
    int lr = ltid >> 3, lkq = ltid & 7;
    float* gd = dyn + grp * GRP_F;
    int h0 = (blockIdx.x & 31) * 16;
    int m0 = (blockIdx.x >> 5) * 32;

    ull acc[8];
#pragma unroll
    for (int i = 0; i < 8; i++) acc[i] = 0;

    float4 av[2], wv[4];
    auto load = [&](int kb) {
        int vk0 = grp * 160 + kb * 32;
        int isx = vk0 < DD;
        int kp = (isx ? vk0 : vk0 - DD) + lkq * 4;
#pragma unroll
        for (int j = 0; j < 2; j++) {
            int m = m0 + lr + 16 * j;
            const float* p = isx ? (x + ((size_t)m * TT + t) * DD + kp)
                                 : (hin + (size_t)m * HH + kp);
            av[j] = *(const float4*)p;
        }
#pragma unroll
        for (int j = 0; j < 4; j++) {
            int c = lr + 16 * j;
            int wcol = (c >> 4) * HH + h0 + (c & 15);
            const float* p = isx ? (Wih + (size_t)wcol * DD + kp)
                                 : (Whh + (size_t)wcol * HH + kp);
            wv[j] = *(const float4*)p;
        }
    };

    load(0);
    for (int kb = 0; kb < 5; kb++) {
        float* Ab = gd + (kb & 1) * A_BUF;
        float* Wb = gd + 2 * A_BUF + (kb & 1) * W_BUF;
#pragma unroll
        for (int j = 0; j < 2; j++) stA32(Ab, av[j], lkq, lr + 16 * j);
#pragma unroll
        for (int j = 0; j < 4; j++) stW64(Wb, wv[j], lkq, lr + 16 * j);
        gbar(grp);
        if (kb + 1 < 5) load(kb + 1);
        kfma32(Ab, Wb, tx, ty, acc);
    }

    __syncthreads();
    if (grp > 0) red_write<8>(dyn, grp, ltid, acc);
    __syncthreads();
    if (grp == 0) {
        red_accum<8>(dyn, ltid, acc);
        int bcol = ((4 * tx) >> 4) * HH + h0 + ((4 * tx) & 15);
        float4 bi = *(const float4*)(bih + bcol);
        float4 bh = *(const float4*)(bhh + bcol);
#pragma unroll
        for (int r = 0; r < 4; r++) {
            float2 lo = unpack2(acc[r * 2]), hi = unpack2(acc[r * 2 + 1]);
            float4 o = make_float4(lo.x + bi.x + bh.x, lo.y + bi.y + bh.y,
                                   hi.x + bi.z + bh.z, hi.y + bi.w + bh.w);
            *(float4*)&Gs[4 * ty + r][4 * tx] = o;
        }
    }
    __syncthreads();

    // elementwise c/h update: 512 elems, 1 per thread
    int rr = tid >> 4, jj = tid & 15;
    float iv = sigmoidf_(Gs[rr][jj]);
    float fv = sigmoidf_(Gs[rr][16 + jj]);
    float gv = tanhf(Gs[rr][32 + jj]);
    float ov = sigmoidf_(Gs[rr][48 + jj]);
    int idx = (m0 + rr) * HH + h0 + jj;
    float cn = fv * g_c[idx] + iv * gv;
    g_c[idx] = cn;
    hout[idx] = ov * tanhf(cn);
    __syncthreads();
}

// ---------------- mega persistent kernel (single graph node) ------------------------
__global__ __launch_bounds__(NTHR, 1) void mega_kernel(
    const float* __restrict__ x,
    const float* __restrict__ Wih, const float* __restrict__ Whh,
    const float* __restrict__ bih, const float* __restrict__ bhh,
    const float* __restrict__ ow1, const float* __restrict__ ob1,
    const float* __restrict__ ow2, const float* __restrict__ ob2,
    const float* __restrict__ ow3, const float* __restrict__ ob3,
    const float* __restrict__ dw1, const float* __restrict__ db1,
    const float* __restrict__ dw2, const float* __restrict__ db2,
    float* __restrict__ out)
{
    extern __shared__ float dyn[];
    __shared__ float Gs[32][64];

    int tid = threadIdx.x;
    int gidx = blockIdx.x * NTHR + tid;   // 65536 threads == BB*HH

    g_h[0][gidx] = 0.f;
    g_c[gidx] = 0.f;
    gsync();

    // ---- LSTM encoder: 1024 steps ----
    for (int t = 0; t < TT; t++) {
        const float* hin = (t & 1) ? g_h[1] : g_h[0];
        float* hout      = (t & 1) ? g_h[0] : g_h[1];
        lstm4(dyn, Gs, x, Wih, Whh, bih, bhh, hin, hout, t);
        gsync();
    }

    // ---- z0 = c_n; pred slot 0 ----
    {
        float v = g_c[gidx];
        g_z[gidx] = v;
        int bb = gidx >> 9, hh = gidx & 511;
        g_pred[(bb * 5) * HH + hh] = v;
    }
    gsync();

    // ---- latent ODE: 32 RK4 substeps ----
    const double dtd = (5.0 / 60.0) / 8.0;
    const float dtf  = (float)dtd;
    const float half = (float)(0.5 * dtd);
    const float dt6  = (float)(dtd / 6.0);

    for (int step = 0; step < 32; step++) {
        gemm_g<1, false, 16>(dyn, g_z, nullptr, 0.f, ow1, ob1, g_t1, BB, NHID, HH); gsync();
        gemm_g<1, false, 16>(dyn, g_t1, nullptr, 0.f, ow2, ob2, g_t2, BB, NHID, NHID); gsync();
        gemm_g<0, false, 16>(dyn, g_t2, nullptr, 0.f, ow3, ob3, g_k[0], BB, HH, NHID); gsync();

        gemm_g<1, true, 16>(dyn, g_z, g_k[0], half, ow1, ob1, g_t1, BB, NHID, HH); gsync();
        gemm_g<1, false, 16>(dyn, g_t1, nullptr, 0.f, ow2, ob2, g_t2, BB, NHID, NHID); gsync();
        gemm_g<0, false, 16>(dyn, g_t2, nullptr, 0.f, ow3, ob3, g_k[1], BB, HH, NHID); gsync();

        gemm_g<1, true, 16>(dyn, g_z, g_k[1], half, ow1, ob1, g_t1, BB, NHID, HH); gsync();
        gemm_g<1, false, 16>(dyn, g_t1, nullptr, 0.f, ow2, ob2, g_t2, BB, NHID, NHID); gsync();
        gemm_g<0, false, 16>(dyn, g_t2, nullptr, 0.f, ow3, ob3, g_k[2], BB, HH, NHID); gsync();

        gemm_g<1, true, 16>(dyn, g_z, g_k[2], dtf, ow1, ob1, g_t1, BB, NHID, HH); gsync();
        gemm_g<1, false, 16>(dyn, g_t1, nullptr, 0.f, ow2, ob2, g_t2, BB, NHID, NHID); gsync();
        gemm_g<0, false, 16>(dyn, g_t2, nullptr, 0.f, ow3, ob3, g_k[3], BB, HH, NHID); gsync();

        {
            float z = g_z[gidx] + dt6 * (g_k[0][gidx] + 2.f * (g_k[1][gidx] + g_k[2][gidx]) + g_k[3][gidx]);
            g_z[gidx] = z;
            if ((step & 7) == 7) {
                int bb = gidx >> 9, hh = gidx & 511;
                g_pred[(bb * 5 + (step >> 3) + 1) * HH + hh] = z;
            }
        }
        gsync();
    }

    // ---- decoder ----
    gemm_g<2, false, 32>(dyn, g_pred, nullptr, 0.f, dw1, db1, g_dec1, BB * 5, NHID, HH);
    gsync();
    gemm_g<0, false, 32>(dyn, g_dec1, nullptr, 0.f, dw2, db2, out, BB * 5, DD, NHID);
}

// ---------------- host side -----------------------------------------------------------
extern "C" void kernel_launch(void* const* d_in, const int* in_sizes, int n_in,
                              void* d_out, int out_size)
{
    const float* inputs = (const float*)d_in[0];

    // Locate W_ih robustly: 4*512*128 elems followed by 4*512*512.
    int p = 2;
    for (int i = 1; i + 1 < n_in; i++) {
        if (in_sizes[i] == 4 * HH * DD && in_sizes[i + 1] == 4 * HH * HH) { p = i; break; }
    }
    const float* W_ih = (const float*)d_in[p + 0];
    const float* W_hh = (const float*)d_in[p + 1];
    const float* b_ih = (const float*)d_in[p + 2];
    const float* b_hh = (const float*)d_in[p + 3];
    const float* ow1 = (const float*)d_in[p + 4];
    const float* ob1 = (const float*)d_in[p + 5];
    const float* ow2 = (const float*)d_in[p + 6];
    const float* ob2 = (const float*)d_in[p + 7];
    const float* ow3 = (const float*)d_in[p + 8];
    const float* ob3 = (const float*)d_in[p + 9];
    const float* dw1 = (const float*)d_in[p + 10];
    const float* db1 = (const float*)d_in[p + 11];
    const float* dw2 = (const float*)d_in[p + 12];
    const float* db2 = (const float*)d_in[p + 13];

    cudaFuncSetAttribute(mega_kernel, cudaFuncAttributeMaxDynamicSharedMemorySize,
                         DYN_BYTES);

    mega_kernel<<<GRID, NTHR, DYN_BYTES>>>(inputs, W_ih, W_hh, b_ih, b_hh,
                                           ow1, ob1, ow2, ob2, ow3, ob3,
                                           dw1, db1, dw2, db2, (float*)d_out);
}

// round 12
// speedup vs baseline: 2.2133x; 1.4122x over previous
#include <cuda_runtime.h>
#include <math.h>
#include <stdint.h>

#define BB   128
#define TT   1024
#define DD   128
#define HH   512
#define NHID 1024
#define GRID 128
#define NTHR 512
#define NGRP 4

typedef unsigned long long ull;

// ---- SIMT (ODE) smem layout ----
#define A_BUF 1024
#define W_BUF 2048
#define GRP_F (2 * A_BUF + 2 * W_BUF)
#define ODE_BYTES (NGRP * GRP_F * 4)
// ---- LSTM MMA smem layout: W resident 64x644 f32 + 4 A-buffers 32x68 ----
#define WS   644
#define AS   68
#define WSM_BYTES (64 * WS * 4)          /* 164864 */
#define ABUF_FLTS (32 * AS)              /* 2176 */
#define LSTM_DYN (WSM_BYTES + 4 * ABUF_FLTS * 4)   /* 199680 */
#define DYN_BYTES (LSTM_DYN > ODE_BYTES ? LSTM_DYN : ODE_BYTES)

__device__ float g_h[2][BB * HH];
__device__ float g_c[BB * HH];
__device__ float g_z[BB * HH];
__device__ float g_k[4][BB * HH];
__device__ float g_t1[BB * NHID];
__device__ float g_t2[BB * NHID];
__device__ float g_pred[BB * 5 * HH];
__device__ float g_dec1[BB * 5 * NHID];

__device__ unsigned g_cnt = 0;
__device__ volatile unsigned g_gen = 0;

__device__ __forceinline__ void gsync() {
    __threadfence();
    __syncthreads();
    if (threadIdx.x == 0) {
        unsigned gen = g_gen;
        if (atomicAdd(&g_cnt, 1u) == GRID - 1) {
            g_cnt = 0;
            __threadfence();
            g_gen = gen + 1;
        } else {
            while (g_gen == gen) { }
        }
    }
    __syncthreads();
    __threadfence();
}

__device__ __forceinline__ void fma2(ull& acc, ull a, ull b) {
    asm("fma.rn.f32x2 %0, %1, %2, %0;" : "+l"(acc) : "l"(a), "l"(b));
}
__device__ __forceinline__ ull addf2(ull a, ull b) {
    ull r; asm("add.rn.f32x2 %0, %1, %2;" : "=l"(r) : "l"(a), "l"(b)); return r;
}
__device__ __forceinline__ ull pack2(float x) {
    ull r; asm("mov.b64 %0, {%1, %1};" : "=l"(r) : "f"(x)); return r;
}
__device__ __forceinline__ float2 unpack2(ull v) {
    float2 r; asm("mov.b64 {%0, %1}, %2;" : "=f"(r.x), "=f"(r.y) : "l"(v)); return r;
}
__device__ __forceinline__ float sigmoidf_(float x) { return 1.f / (1.f + expf(-x)); }
__device__ __forceinline__ float eluf_(float x)     { return x > 0.f ? x : expm1f(x); }

__device__ __forceinline__ void gbar(int grp) {
    asm volatile("bar.sync %0, 128;" :: "r"(grp + 1) : "memory");
}

// ---------------- async-copy / tf32 helpers ------------------------------------
__device__ __forceinline__ uint32_t smem_u32(const void* p) {
    uint32_t a;
    asm("{ .reg .u64 t; cvta.to.shared.u64 t, %1; cvt.u32.u64 %0, t; }" : "=r"(a) : "l"(p));
    return a;
}
__device__ __forceinline__ void cpasync16(uint32_t dst, const void* src) {
    asm volatile("cp.async.cg.shared.global [%0], [%1], 16;" :: "r"(dst), "l"(src));
}
__device__ __forceinline__ void cp_commit() {
    asm volatile("cp.async.commit_group;" ::: "memory");
}
template <int N>
__device__ __forceinline__ void cp_wait() {
    asm volatile("cp.async.wait_group %0;" :: "n"(N) : "memory");
}
__device__ __forceinline__ float tf32r(float x) {
    uint32_t r; asm("cvt.rna.tf32.f32 %0, %1;" : "=r"(r) : "f"(x));
    return __uint_as_float(r);
}
// m16n8k8 tf32 warp MMA (sm_80 baseline HMMA path -- valid on sm_103 target)
__device__ __forceinline__ void mma8(float* d, uint32_t a0, uint32_t a1,
                                     uint32_t a2, uint32_t a3,
                                     uint32_t b0, uint32_t b1) {
    asm volatile(
        "mma.sync.aligned.m16n8k8.row.col.f32.tf32.tf32.f32 "
        "{%0,%1,%2,%3}, {%4,%5,%6,%7}, {%8,%9}, {%0,%1,%2,%3};"
        : "+f"(d[0]), "+f"(d[1]), "+f"(d[2]), "+f"(d[3])
        : "r"(a0), "r"(a1), "r"(a2), "r"(a3), "r"(b0), "r"(b1));
}

// ---------------- SIMT GEMM path (unchanged from R9; ODE + decoder) -------------
__device__ __forceinline__ void stA32(float* Ab, float4 v, int lkq, int r) {
    float* p = Ab + lkq * 4 * 32 + ((((r >> 2) ^ lkq) & 7) << 2) + (r & 3);
    p[0] = v.x; p[32] = v.y; p[64] = v.z; p[96] = v.w;
}
__device__ __forceinline__ void stA16(float* Ab, float4 v, int lkq, int r) {
    float* p = Ab + lkq * 4 * 16 + ((((r >> 2) ^ lkq) & 3) << 2) + (r & 3);
    p[0] = v.x; p[16] = v.y; p[32] = v.z; p[48] = v.w;
}
__device__ __forceinline__ void stW64(float* Wb, float4 v, int lkq, int col) {
    float* p = Wb + lkq * 4 * 64 + ((((col >> 2) ^ lkq) & 15) << 2) + (col & 3);
    p[0] = v.x; p[64] = v.y; p[128] = v.z; p[192] = v.w;
}
__device__ __forceinline__ void kfma32(const float* Ab, const float* Wb,
                                       int tx, int ty, ull* acc) {
#pragma unroll
    for (int k = 0; k < 32; k++) {
        const int c = k >> 2;
        float4 a = *(const float4*)&Ab[k * 32 + (((ty ^ c) & 7) << 2)];
        ulonglong2 w = *(const ulonglong2*)&Wb[k * 64 + (((tx ^ c) & 15) << 2)];
        ull ax = pack2(a.x), ay = pack2(a.y), az = pack2(a.z), aw = pack2(a.w);
        fma2(acc[0], ax, w.x); fma2(acc[1], ax, w.y);
        fma2(acc[2], ay, w.x); fma2(acc[3], ay, w.y);
        fma2(acc[4], az, w.x); fma2(acc[5], az, w.y);
        fma2(acc[6], aw, w.x); fma2(acc[7], aw, w.y);
    }
}
__device__ __forceinline__ void kfma16(const float* Ab, const float* Wb,
                                       int tx, int ty, ull* acc) {
#pragma unroll
    for (int k = 0; k < 32; k++) {
        const int c = k >> 2;
        float2 a = *(const float2*)&Ab[k * 16 + ((((ty >> 1) ^ c) & 3) << 2) + ((ty & 1) << 1)];
        ulonglong2 w = *(const ulonglong2*)&Wb[k * 64 + (((tx ^ c) & 15) << 2)];
        ull ax = pack2(a.x), ay = pack2(a.y);
        fma2(acc[0], ax, w.x); fma2(acc[1], ax, w.y);
        fma2(acc[2], ay, w.x); fma2(acc[3], ay, w.y);
    }
}
template <int NACC>
__device__ __forceinline__ void red_write(float* dyn, int grp, int ltid, ull* acc) {
    ull* rg = (ull*)(dyn + grp * GRP_F);
#pragma unroll
    for (int i = 0; i < NACC; i++) rg[i * 128 + ltid] = acc[i];
}
template <int NACC>
__device__ __forceinline__ void red_accum(float* dyn, int ltid, ull* acc) {
#pragma unroll
    for (int g = 1; g < NGRP; g++) {
        ull* rg = (ull*)(dyn + g * GRP_F);
#pragma unroll
        for (int i = 0; i < NACC; i++) acc[i] = addf2(acc[i], rg[i * 128 + ltid]);
    }
}
template <int ACT, bool HASA2, int BM>
__device__ void gemm_g(float* dyn, const float* __restrict__ A,
                       const float* __restrict__ A2, float alpha,
                       const float* __restrict__ W, const float* __restrict__ bias,
                       float* __restrict__ C, int M, int N, int K)
{
    constexpr int AV = BM / 16;
    constexpr int NACC = BM / 4;
    constexpr int RPT = BM / 8;

    const int tid = threadIdx.x;
    const int grp = tid >> 7, ltid = tid & 127;
    const int tx = ltid & 15, ty = ltid >> 4;
    const int lr = ltid >> 3, lkq = ltid & 7;
    float* gd = dyn + grp * GRP_F;
    const int kgrp = K >> 2, nkb = kgrp >> 5;
    const int koff0 = grp * kgrp + lkq * 4;
    const int ntiles = N >> 6;
    const int total = ntiles * (M / BM);

    for (int tile = blockIdx.x; tile < total; tile += GRID) {
        int n0 = (tile % ntiles) << 6;
        int m0 = (tile / ntiles) * BM;

        ull acc[NACC];
#pragma unroll
        for (int i = 0; i < NACC; i++) acc[i] = 0;

        float4 av[AV], wv[4];
#pragma unroll
        for (int j = 0; j < AV; j++) {
            const float* p = A + (size_t)(m0 + lr + 16 * j) * K + koff0;
            float4 v = *(const float4*)p;
            if (HASA2) {
                float4 v2 = *(const float4*)(A2 + (size_t)(m0 + lr + 16 * j) * K + koff0);
                v.x = fmaf(alpha, v2.x, v.x); v.y = fmaf(alpha, v2.y, v.y);
                v.z = fmaf(alpha, v2.z, v.z); v.w = fmaf(alpha, v2.w, v.w);
            }
            av[j] = v;
        }
#pragma unroll
        for (int j = 0; j < 4; j++)
            wv[j] = *(const float4*)(W + (size_t)(n0 + lr + 16 * j) * K + koff0);

        for (int kb = 0; kb < nkb; kb++) {
            float* Ab = gd + (kb & 1) * A_BUF;
            float* Wb = gd + 2 * A_BUF + (kb & 1) * W_BUF;
#pragma unroll
            for (int j = 0; j < AV; j++) {
                if (BM == 32) stA32(Ab, av[j], lkq, lr + 16 * j);
                else          stA16(Ab, av[j], lkq, lr);
            }
#pragma unroll
            for (int j = 0; j < 4; j++) stW64(Wb, wv[j], lkq, lr + 16 * j);
            gbar(grp);
            if (kb + 1 < nkb) {
                int ko = koff0 + (kb + 1) * 32;
#pragma unroll
                for (int j = 0; j < AV; j++) {
                    const float* p = A + (size_t)(m0 + lr + 16 * j) * K + ko;
                    float4 v = *(const float4*)p;
                    if (HASA2) {
                        float4 v2 = *(const float4*)(A2 + (size_t)(m0 + lr + 16 * j) * K + ko);
                        v.x = fmaf(alpha, v2.x, v.x); v.y = fmaf(alpha, v2.y, v.y);
                        v.z = fmaf(alpha, v2.z, v.z); v.w = fmaf(alpha, v2.w, v.w);
                    }
                    av[j] = v;
                }
#pragma unroll
                for (int j = 0; j < 4; j++)
                    wv[j] = *(const float4*)(W + (size_t)(n0 + lr + 16 * j) * K + ko);
            }
            if (BM == 32) kfma32(Ab, Wb, tx, ty, acc);
            else          kfma16(Ab, Wb, tx, ty, acc);
        }

        __syncthreads();
        if (grp > 0) red_write<NACC>(dyn, grp, ltid, acc);
        __syncthreads();
        if (grp == 0) {
            red_accum<NACC>(dyn, ltid, acc);
            float4 bv = *(const float4*)(bias + n0 + 4 * tx);
#pragma unroll
            for (int r = 0; r < RPT; r++) {
                int row = m0 + RPT * ty + r;
                float2 lo = unpack2(acc[r * 2]), hi = unpack2(acc[r * 2 + 1]);
                float4 o = make_float4(lo.x + bv.x, lo.y + bv.y, hi.x + bv.z, hi.y + bv.w);
                if (ACT == 1) {
                    o.x = eluf_(o.x); o.y = eluf_(o.y);
                    o.z = eluf_(o.z); o.w = eluf_(o.w);
                }
                if (ACT == 2) {
                    o.x = fmaxf(o.x, 0.f); o.y = fmaxf(o.y, 0.f);
                    o.z = fmaxf(o.z, 0.f); o.w = fmaxf(o.w, 0.f);
                }
                *(float4*)(C + (size_t)row * N + n0 + 4 * tx) = o;
            }
        }
        __syncthreads();
    }
}

// ---------------- warp-MMA tf32 LSTM step ----------------------------------------
// CTA tile: 32 batch rows x 64 gate cols (col c -> W row (c>>4)*HH + h0 + (c&15)).
// A = [x_t | h] streamed as 10 chunks [32 x 64k], stride 68; W resident stride 644.
// Warps 0-7 compute (warp-tile 16x16: rt=wid&1, ct=wid>>1); all warps copy.
__device__ void lstm_mma(int t, const float* __restrict__ x,
                         const float* __restrict__ hin, float* __restrict__ hout,
                         float* Wsm, float* Abufs, float (*Gs)[AS],
                         const float* bsum, int m0, int h0)
{
    const int tid = threadIdx.x;
    const int wid = tid >> 5, lane = tid & 31;
    const int row = tid >> 4, q = tid & 15;     // copy mapping: 1x16B per thread

    auto load_chunk = [&](int c) {
        float* dst = Abufs + (c & 3) * ABUF_FLTS + row * AS + q * 4;
        const float* src = (c < 2)
            ? x + ((size_t)(m0 + row) * TT + t) * DD + c * 64 + q * 4
            : hin + (size_t)(m0 + row) * HH + (c - 2) * 64 + q * 4;
        cpasync16(smem_u32(dst), src);
        cp_commit();
    };

    load_chunk(0); load_chunk(1); load_chunk(2);

    float d[8];
#pragma unroll
    for (int i = 0; i < 8; i++) d[i] = 0.f;

    const int crt = wid & 1, cct = wid >> 1;
    const int gr = lane >> 2, tg = lane & 3;
    const int aoff = (crt * 16 + gr) * AS + tg;
    const int boff0 = (cct * 16 + gr) * WS + tg;
    const int boff1 = (cct * 16 + 8 + gr) * WS + tg;

    for (int c = 0; c < 10; c++) {
        if (c < 8) cp_wait<2>();
        else if (c == 8) cp_wait<1>();
        else cp_wait<0>();

        if (c < 2) {   // tf32-round the x chunk in place (own 16B only)
            float* pch = Abufs + (c & 3) * ABUF_FLTS + row * AS + q * 4;
            float4 v = *(float4*)pch;
            v.x = tf32r(v.x); v.y = tf32r(v.y); v.z = tf32r(v.z); v.w = tf32r(v.w);
            *(float4*)pch = v;
        }
        __syncthreads();
        if (c < 7) load_chunk(c + 3);

        if (wid < 8) {
            const float* Ab = Abufs + (c & 3) * ABUF_FLTS;
            const float* Wb = Wsm + c * 64;
#pragma unroll
            for (int s = 0; s < 8; s++) {
                const float* ap = Ab + aoff + s * 8;
                uint32_t a0 = __float_as_uint(ap[0]);
                uint32_t a1 = __float_as_uint(ap[8 * AS]);
                uint32_t a2 = __float_as_uint(ap[4]);
                uint32_t a3 = __float_as_uint(ap[8 * AS + 4]);
                const float* bp0 = Wb + boff0 + s * 8;
                uint32_t b0 = __float_as_uint(bp0[0]);
                uint32_t b1 = __float_as_uint(bp0[4]);
                mma8(d, a0, a1, a2, a3, b0, b1);
                const float* bp1 = Wb + boff1 + s * 8;
                uint32_t b2 = __float_as_uint(bp1[0]);
                uint32_t b3 = __float_as_uint(bp1[4]);
                mma8(d + 4, a0, a1, a2, a3, b2, b3);
            }
        }
    }

    // D -> Gs
    if (wid < 8) {
        int r0 = crt * 16 + gr;
        int c0 = cct * 16 + 2 * tg;
        Gs[r0][c0] = d[0];     Gs[r0][c0 + 1] = d[1];
        Gs[r0 + 8][c0] = d[2]; Gs[r0 + 8][c0 + 1] = d[3];
        Gs[r0][c0 + 8] = d[4];     Gs[r0][c0 + 9] = d[5];
        Gs[r0 + 8][c0 + 8] = d[6]; Gs[r0 + 8][c0 + 9] = d[7];
    }
    __syncthreads();

    // elementwise c/h update: 512 elems, 1 per thread
    int rr = tid >> 4, jj = tid & 15;
    float iv = sigmoidf_(Gs[rr][jj] + bsum[jj]);
    float fv = sigmoidf_(Gs[rr][16 + jj] + bsum[16 + jj]);
    float gv = tanhf(Gs[rr][32 + jj] + bsum[32 + jj]);
    float ov = sigmoidf_(Gs[rr][48 + jj] + bsum[48 + jj]);
    int idx = (m0 + rr) * HH + h0 + jj;
    float cn = fv * g_c[idx] + iv * gv;
    g_c[idx] = cn;
    hout[idx] = tf32r(ov * tanhf(cn));     // h pre-rounded for next step's MMA
    __syncthreads();
}

// ---------------- mega persistent kernel (single graph node) ----------------------
__global__ __launch_bounds__(NTHR, 1) void mega_kernel(
    const float* __restrict__ x,
    const float* __restrict__ Wih, const float* __restrict__ Whh,
    const float* __restrict__ bih, const float* __restrict__ bhh,
    const float* __restrict__ ow1, const float* __restrict__ ob1,
    const float* __restrict__ ow2, const float* __restrict__ ob2,
    const float* __restrict__ ow3, const float* __restrict__ ob3,
    const float* __restrict__ dw1, const float* __restrict__ db1,
    const float* __restrict__ dw2, const float* __restrict__ db2,
    float* __restrict__ out)
{
    extern __shared__ float dyn[];
    __shared__ float Gs[32][AS];
    __shared__ float s_bsum[64];

    const int tid = threadIdx.x;
    const int gidx = blockIdx.x * NTHR + tid;
    const int h0 = (blockIdx.x & 31) * 16;
    const int m0 = (blockIdx.x >> 5) * 32;

    g_h[0][gidx] = 0.f;
    g_c[gidx] = 0.f;

    // ---- LSTM setup: resident W (tf32-rounded, stride 644) + bias sums ----
    float* Wsm = dyn;
    float* Abufs = dyn + WSM_BYTES / 4;
    for (int e = tid; e < 64 * 160; e += NTHR) {
        int c = e / 160, w4 = e % 160;
        int kg = w4 * 4;
        int wr = (c >> 4) * HH + h0 + (c & 15);
        float4 v = (kg < DD) ? *(const float4*)(Wih + (size_t)wr * DD + kg)
                             : *(const float4*)(Whh + (size_t)wr * HH + (kg - DD));
        v.x = tf32r(v.x); v.y = tf32r(v.y); v.z = tf32r(v.z); v.w = tf32r(v.w);
        *(float4*)(Wsm + c * WS + kg) = v;
    }
    if (tid < 64) {
        int wr = (tid >> 4) * HH + h0 + (tid & 15);
        s_bsum[tid] = bih[wr] + bhh[wr];
    }
    gsync();

    // ---- LSTM encoder: 1024 steps on HMMA tf32 ----
    for (int t = 0; t < TT; t++) {
        const float* hin = (t & 1) ? g_h[1] : g_h[0];
        float* hout      = (t & 1) ? g_h[0] : g_h[1];
        lstm_mma(t, x, hin, hout, Wsm, Abufs, Gs, s_bsum, m0, h0);
        gsync();
    }

    // ---- z0 = c_n; pred slot 0 ----
    {
        float v = g_c[gidx];
        g_z[gidx] = v;
        int bb = gidx >> 9, hh = gidx & 511;
        g_pred[(bb * 5) * HH + hh] = v;
    }
    gsync();

    // ---- latent ODE: 32 RK4 substeps (SIMT f32x2 GEMMs) ----
    const double dtd = (5.0 / 60.0) / 8.0;
    const float dtf  = (float)dtd;
    const float half = (float)(0.5 * dtd);
    const float dt6  = (float)(dtd / 6.0);

    for (int step = 0; step < 32; step++) {
        gemm_g<1, false, 16>(dyn, g_z, nullptr, 0.f, ow1, ob1, g_t1, BB, NHID, HH); gsync();
        gemm_g<1, false, 16>(dyn, g_t1, nullptr, 0.f, ow2, ob2, g_t2, BB, NHID, NHID); gsync();
        gemm_g<0, false, 16>(dyn, g_t2, nullptr, 0.f, ow3, ob3, g_k[0], BB, HH, NHID); gsync();

        gemm_g<1, true, 16>(dyn, g_z, g_k[0], half, ow1, ob1, g_t1, BB, NHID, HH); gsync();
        gemm_g<1, false, 16>(dyn, g_t1, nullptr, 0.f, ow2, ob2, g_t2, BB, NHID, NHID); gsync();
        gemm_g<0, false, 16>(dyn, g_t2, nullptr, 0.f, ow3, ob3, g_k[1], BB, HH, NHID); gsync();

        gemm_g<1, true, 16>(dyn, g_z, g_k[1], half, ow1, ob1, g_t1, BB, NHID, HH); gsync();
        gemm_g<1, false, 16>(dyn, g_t1, nullptr, 0.f, ow2, ob2, g_t2, BB, NHID, NHID); gsync();
        gemm_g<0, false, 16>(dyn, g_t2, nullptr, 0.f, ow3, ob3, g_k[2], BB, HH, NHID); gsync();

        gemm_g<1, true, 16>(dyn, g_z, g_k[2], dtf, ow1, ob1, g_t1, BB, NHID, HH); gsync();
        gemm_g<1, false, 16>(dyn, g_t1, nullptr, 0.f, ow2, ob2, g_t2, BB, NHID, NHID); gsync();
        gemm_g<0, false, 16>(dyn, g_t2, nullptr, 0.f, ow3, ob3, g_k[3], BB, HH, NHID); gsync();

        {
            float z = g_z[gidx] + dt6 * (g_k[0][gidx] + 2.f * (g_k[1][gidx] + g_k[2][gidx]) + g_k[3][gidx]);
            g_z[gidx] = z;
            if ((step & 7) == 7) {
                int bb = gidx >> 9, hh = gidx & 511;
                g_pred[(bb * 5 + (step >> 3) + 1) * HH + hh] = z;
            }
        }
        gsync();
    }

    // ---- decoder ----
    gemm_g<2, false, 32>(dyn, g_pred, nullptr, 0.f, dw1, db1, g_dec1, BB * 5, NHID, HH);
    gsync();
    gemm_g<0, false, 32>(dyn, g_dec1, nullptr, 0.f, dw2, db2, out, BB * 5, DD, NHID);
}

// ---------------- host side --------------------------------------------------------
extern "C" void kernel_launch(void* const* d_in, const int* in_sizes, int n_in,
                              void* d_out, int out_size)
{
    const float* inputs = (const float*)d_in[0];

    int p = 2;
    for (int i = 1; i + 1 < n_in; i++) {
        if (in_sizes[i] == 4 * HH * DD && in_sizes[i + 1] == 4 * HH * HH) { p = i; break; }
    }
    const float* W_ih = (const float*)d_in[p + 0];
    const float* W_hh = (const float*)d_in[p + 1];
    const float* b_ih = (const float*)d_in[p + 2];
    const float* b_hh = (const float*)d_in[p + 3];
    const float* ow1 = (const float*)d_in[p + 4];
    const float* ob1 = (const float*)d_in[p + 5];
    const float* ow2 = (const float*)d_in[p + 6];
    const float* ob2 = (const float*)d_in[p + 7];
    const float* ow3 = (const float*)d_in[p + 8];
    const float* ob3 = (const float*)d_in[p + 9];
    const float* dw1 = (const float*)d_in[p + 10];
    const float* db1 = (const float*)d_in[p + 11];
    const float* dw2 = (const float*)d_in[p + 12];
    const float* db2 = (const float*)d_in[p + 13];

    cudaFuncSetAttribute(mega_kernel, cudaFuncAttributeMaxDynamicSharedMemorySize,
                         DYN_BYTES);

    mega_kernel<<<GRID, NTHR, DYN_BYTES>>>(inputs, W_ih, W_hh, b_ih, b_hh,
                                           ow1, ob1, ow2, ob2, ow3, ob3,
                                           dw1, db1, dw2, db2, (float*)d_out);
}

// round 13
// speedup vs baseline: 2.9029x; 1.3116x over previous
#include <cuda_runtime.h>
#include <math.h>
#include <stdint.h>

#define BB   128
#define TT   1024
#define DD   128
#define HH   512
#define NHID 1024
#define GRID 128
#define NTHR 512
#define NGRP 4

typedef unsigned long long ull;

// ---- SIMT (decoder) smem layout ----
#define A_BUF 1024
#define W_BUF 2048
#define GRP_F (2 * A_BUF + 2 * W_BUF)
// ---- ODE MMA smem layout: per group 2x(16x36) A + 2x(64x36) W ----
#define AS2 36
#define GRP2_F (2 * 16 * AS2 + 2 * 64 * AS2)   /* 5760 floats */
// ---- LSTM MMA smem: W resident 64x644 + 4 h-ring (32x68) + 2 x-buf (32x68) ----
#define WS   644
#define AS   68
#define ABUF_FLTS (32 * AS)                    /* 2176 */
#define WSM_FLTS  (64 * WS)                    /* 41216 */
#define LSTM_FLTS (WSM_FLTS + 6 * ABUF_FLTS)   /* 54272 */
#define DYN_BYTES (LSTM_FLTS * 4)              /* 217088 */

__device__ float g_h[2][BB * HH];
__device__ float g_c[BB * HH];
__device__ float g_z[BB * HH];
__device__ float g_k[4][BB * HH];
__device__ float g_t1[BB * NHID];
__device__ float g_t2[BB * NHID];
__device__ float g_pred[BB * 5 * HH];
__device__ float g_dec1[BB * 5 * NHID];

__device__ unsigned g_cnt = 0;
__device__ volatile unsigned g_gen = 0;

// ---------------- slim grid barrier (CG-style: 1-thread fence) -----------------
__device__ __forceinline__ void gsync() {
    __syncthreads();
    if (threadIdx.x == 0) {
        unsigned gen = g_gen;
        asm volatile("fence.acq_rel.gpu;" ::: "memory");
        if (atomicAdd(&g_cnt, 1u) == gen * GRID + (GRID - 1)) {
            g_gen = gen + 1;
        } else {
            while (g_gen == gen) { }
        }
        asm volatile("fence.acq_rel.gpu;" ::: "memory");
    }
    __syncthreads();
}

// ---------------- packed f32x2 helpers (decoder SIMT path) ---------------------
__device__ __forceinline__ void fma2(ull& acc, ull a, ull b) {
    asm("fma.rn.f32x2 %0, %1, %2, %0;" : "+l"(acc) : "l"(a), "l"(b));
}
__device__ __forceinline__ ull addf2(ull a, ull b) {
    ull r; asm("add.rn.f32x2 %0, %1, %2;" : "=l"(r) : "l"(a), "l"(b)); return r;
}
__device__ __forceinline__ ull pack2(float x) {
    ull r; asm("mov.b64 %0, {%1, %1};" : "=l"(r) : "f"(x)); return r;
}
__device__ __forceinline__ float2 unpack2(ull v) {
    float2 r; asm("mov.b64 {%0, %1}, %2;" : "=f"(r.x), "=f"(r.y) : "l"(v)); return r;
}
__device__ __forceinline__ float sigmoidf_(float x) { return 1.f / (1.f + expf(-x)); }
__device__ __forceinline__ float eluf_(float x)     { return x > 0.f ? x : expm1f(x); }

__device__ __forceinline__ void gbar(int grp) {
    asm volatile("bar.sync %0, 128;" :: "r"(grp + 1) : "memory");
}

// ---------------- async-copy / tf32 / mma helpers ------------------------------
__device__ __forceinline__ uint32_t smem_u32(const void* p) {
    uint32_t a;
    asm("{ .reg .u64 t; cvta.to.shared.u64 t, %1; cvt.u32.u64 %0, t; }" : "=r"(a) : "l"(p));
    return a;
}
__device__ __forceinline__ void cpasync16(uint32_t dst, const void* src) {
    asm volatile("cp.async.cg.shared.global [%0], [%1], 16;" :: "r"(dst), "l"(src));
}
__device__ __forceinline__ void cp_commit() {
    asm volatile("cp.async.commit_group;" ::: "memory");
}
template <int N>
__device__ __forceinline__ void cp_wait() {
    asm volatile("cp.async.wait_group %0;" :: "n"(N) : "memory");
}
__device__ __forceinline__ float tf32r(float x) {
    uint32_t r; asm("cvt.rna.tf32.f32 %0, %1;" : "=r"(r) : "f"(x));
    return __uint_as_float(r);
}
__device__ __forceinline__ float4 tf32r4(float4 v) {
    v.x = tf32r(v.x); v.y = tf32r(v.y); v.z = tf32r(v.z); v.w = tf32r(v.w);
    return v;
}
__device__ __forceinline__ void mma8(float* d, uint32_t a0, uint32_t a1,
                                     uint32_t a2, uint32_t a3,
                                     uint32_t b0, uint32_t b1) {
    asm volatile(
        "mma.sync.aligned.m16n8k8.row.col.f32.tf32.tf32.f32 "
        "{%0,%1,%2,%3}, {%4,%5,%6,%7}, {%8,%9}, {%0,%1,%2,%3};"
        : "+f"(d[0]), "+f"(d[1]), "+f"(d[2]), "+f"(d[3])
        : "r"(a0), "r"(a1), "r"(a2), "r"(a3), "r"(b0), "r"(b1));
}

// ---------------- SIMT GEMM (decoder only) --------------------------------------
__device__ __forceinline__ void stA32(float* Ab, float4 v, int lkq, int r) {
    float* p = Ab + lkq * 4 * 32 + ((((r >> 2) ^ lkq) & 7) << 2) + (r & 3);
    p[0] = v.x; p[32] = v.y; p[64] = v.z; p[96] = v.w;
}
__device__ __forceinline__ void stW64(float* Wb, float4 v, int lkq, int col) {
    float* p = Wb + lkq * 4 * 64 + ((((col >> 2) ^ lkq) & 15) << 2) + (col & 3);
    p[0] = v.x; p[64] = v.y; p[128] = v.z; p[192] = v.w;
}
__device__ __forceinline__ void kfma32(const float* Ab, const float* Wb,
                                       int tx, int ty, ull* acc) {
#pragma unroll
    for (int k = 0; k < 32; k++) {
        const int c = k >> 2;
        float4 a = *(const float4*)&Ab[k * 32 + (((ty ^ c) & 7) << 2)];
        ulonglong2 w = *(const ulonglong2*)&Wb[k * 64 + (((tx ^ c) & 15) << 2)];
        ull ax = pack2(a.x), ay = pack2(a.y), az = pack2(a.z), aw = pack2(a.w);
        fma2(acc[0], ax, w.x); fma2(acc[1], ax, w.y);
        fma2(acc[2], ay, w.x); fma2(acc[3], ay, w.y);
        fma2(acc[4], az, w.x); fma2(acc[5], az, w.y);
        fma2(acc[6], aw, w.x); fma2(acc[7], aw, w.y);
    }
}
template <int ACT>
__device__ void gemm_simt(float* dyn, const float* __restrict__ A,
                          const float* __restrict__ W, const float* __restrict__ bias,
                          float* __restrict__ C, int M, int N, int K)
{
    const int tid = threadIdx.x;
    const int grp = tid >> 7, ltid = tid & 127;
    const int tx = ltid & 15, ty = ltid >> 4;
    const int lr = ltid >> 3, lkq = ltid & 7;
    float* gd = dyn + grp * GRP_F;
    const int kgrp = K >> 2, nkb = kgrp >> 5;
    const int koff0 = grp * kgrp + lkq * 4;
    const int ntiles = N >> 6;
    const int total = ntiles * (M >> 5);

    for (int tile = blockIdx.x; tile < total; tile += GRID) {
        int n0 = (tile % ntiles) << 6;
        int m0 = (tile / ntiles) << 5;

        ull acc[8];
#pragma unroll
        for (int i = 0; i < 8; i++) acc[i] = 0;

        float4 av[2], wv[4];
#pragma unroll
        for (int j = 0; j < 2; j++)
            av[j] = *(const float4*)(A + (size_t)(m0 + lr + 16 * j) * K + koff0);
#pragma unroll
        for (int j = 0; j < 4; j++)
            wv[j] = *(const float4*)(W + (size_t)(n0 + lr + 16 * j) * K + koff0);

        for (int kb = 0; kb < nkb; kb++) {
            float* Ab = gd + (kb & 1) * A_BUF;
            float* Wb = gd + 2 * A_BUF + (kb & 1) * W_BUF;
#pragma unroll
            for (int j = 0; j < 2; j++) stA32(Ab, av[j], lkq, lr + 16 * j);
#pragma unroll
            for (int j = 0; j < 4; j++) stW64(Wb, wv[j], lkq, lr + 16 * j);
            gbar(grp);
            if (kb + 1 < nkb) {
                int ko = koff0 + (kb + 1) * 32;
#pragma unroll
                for (int j = 0; j < 2; j++)
                    av[j] = *(const float4*)(A + (size_t)(m0 + lr + 16 * j) * K + ko);
#pragma unroll
                for (int j = 0; j < 4; j++)
                    wv[j] = *(const float4*)(W + (size_t)(n0 + lr + 16 * j) * K + ko);
            }
            kfma32(Ab, Wb, tx, ty, acc);
        }

        __syncthreads();
        if (grp > 0) {
            ull* rg = (ull*)(dyn + grp * GRP_F);
#pragma unroll
            for (int i = 0; i < 8; i++) rg[i * 128 + ltid] = acc[i];
        }
        __syncthreads();
        if (grp == 0) {
#pragma unroll
            for (int g = 1; g < NGRP; g++) {
                ull* rg = (ull*)(dyn + g * GRP_F);
#pragma unroll
                for (int i = 0; i < 8; i++) acc[i] = addf2(acc[i], rg[i * 128 + ltid]);
            }
            float4 bv = *(const float4*)(bias + n0 + 4 * tx);
#pragma unroll
            for (int r = 0; r < 4; r++) {
                int row = m0 + 4 * ty + r;
                float2 lo = unpack2(acc[r * 2]), hi = unpack2(acc[r * 2 + 1]);
                float4 o = make_float4(lo.x + bv.x, lo.y + bv.y, hi.x + bv.z, hi.y + bv.w);
                if (ACT == 2) {
                    o.x = fmaxf(o.x, 0.f); o.y = fmaxf(o.y, 0.f);
                    o.z = fmaxf(o.z, 0.f); o.w = fmaxf(o.w, 0.f);
                }
                *(float4*)(C + (size_t)row * N + n0 + 4 * tx) = o;
            }
        }
        __syncthreads();
    }
}

// ---------------- MMA GEMM for ODE: C[M,N] = act(tf32(Aeff) @ tf32(W)^T + b) -----
// CTA tile 16 x BN, split-K x4 (4 groups x 4 warps), warp tile 16 x (BN/4).
template <int ACT, bool HASA2, int BN>
__device__ void gemm_mma(float* dyn, const float* __restrict__ A,
                         const float* __restrict__ A2, float alpha,
                         const float* __restrict__ W, const float* __restrict__ bias,
                         float* __restrict__ C, int M, int N, int K)
{
    constexpr int NMMA = BN / 32;          // mmas per warp per s-step (2 or 1)
    constexpr int NACC = 4 * NMMA;
    constexpr int WN4  = BN / 16;          // W float4 loads per thread per kblock

    const int tid = threadIdx.x;
    const int grp = tid >> 7, ltid = tid & 127;
    const int w = ltid >> 5, lane = tid & 31;
    const int gr = lane >> 2, tg = lane & 3;
    float* gd = dyn + grp * GRP2_F;
    float* Ab0 = gd;
    float* Wb0 = gd + 2 * 16 * AS2;
    const int kgrp = K >> 2, nkb = kgrp >> 5;
    const int koff = grp * kgrp;
    const int ntiles = N / BN;
    const int total = ntiles * (M >> 4);
    const int ar = ltid >> 3, aseg = ltid & 7;
    const int wc0 = w * (BN / 4);

    for (int tile = blockIdx.x; tile < total; tile += GRID) {
        int n0 = (tile % ntiles) * BN;
        int m0 = (tile / ntiles) << 4;

        float acc[NACC];
#pragma unroll
        for (int i = 0; i < NACC; i++) acc[i] = 0.f;

        float4 avr;
        float4 wvr[WN4];
        {
            float4 v = *(const float4*)(A + (size_t)(m0 + ar) * K + koff + 4 * aseg);
            if (HASA2) {
                float4 v2 = *(const float4*)(A2 + (size_t)(m0 + ar) * K + koff + 4 * aseg);
                v.x = fmaf(alpha, v2.x, v.x); v.y = fmaf(alpha, v2.y, v.y);
                v.z = fmaf(alpha, v2.z, v.z); v.w = fmaf(alpha, v2.w, v.w);
            }
            avr = tf32r4(v);
#pragma unroll
            for (int i = 0; i < WN4; i++) {
                int flat = ltid + 128 * i;
                int wc = flat >> 3, wseg = flat & 7;
                wvr[i] = tf32r4(*(const float4*)(W + (size_t)(n0 + wc) * K + koff + 4 * wseg));
            }
        }

        for (int kb = 0; kb < nkb; kb++) {
            float* Ab = Ab0 + (kb & 1) * 16 * AS2;
            float* Wb = Wb0 + (kb & 1) * 64 * AS2;
            *(float4*)(Ab + ar * AS2 + 4 * aseg) = avr;
#pragma unroll
            for (int i = 0; i < WN4; i++) {
                int flat = ltid + 128 * i;
                int wc = flat >> 3, wseg = flat & 7;
                *(float4*)(Wb + wc * AS2 + 4 * wseg) = wvr[i];
            }
            gbar(grp);
            if (kb + 1 < nkb) {
                int ko = koff + (kb + 1) * 32;
                float4 v = *(const float4*)(A + (size_t)(m0 + ar) * K + ko + 4 * aseg);
                if (HASA2) {
                    float4 v2 = *(const float4*)(A2 + (size_t)(m0 + ar) * K + ko + 4 * aseg);
                    v.x = fmaf(alpha, v2.x, v.x); v.y = fmaf(alpha, v2.y, v.y);
                    v.z = fmaf(alpha, v2.z, v.z); v.w = fmaf(alpha, v2.w, v.w);
                }
                avr = tf32r4(v);
#pragma unroll
                for (int i = 0; i < WN4; i++) {
                    int flat = ltid + 128 * i;
                    int wc = flat >> 3, wseg = flat & 7;
                    wvr[i] = tf32r4(*(const float4*)(W + (size_t)(n0 + wc) * K + ko + 4 * wseg));
                }
            }
#pragma unroll
            for (int s = 0; s < 4; s++) {
                const float* ap = Ab + gr * AS2 + s * 8 + tg;
                uint32_t a0 = __float_as_uint(ap[0]);
                uint32_t a1 = __float_as_uint(ap[8 * AS2]);
                uint32_t a2 = __float_as_uint(ap[4]);
                uint32_t a3 = __float_as_uint(ap[8 * AS2 + 4]);
#pragma unroll
                for (int j = 0; j < NMMA; j++) {
                    const float* bp = Wb + (wc0 + 8 * j + gr) * AS2 + s * 8 + tg;
                    uint32_t b0 = __float_as_uint(bp[0]);
                    uint32_t b1 = __float_as_uint(bp[4]);
                    mma8(acc + 4 * j, a0, a1, a2, a3, b0, b1);
                }
            }
            gbar(grp);
        }

        __syncthreads();
        if (grp > 0) {
            float* rg = dyn + grp * GRP2_F;
#pragma unroll
            for (int i = 0; i < NACC; i++) rg[i * 128 + ltid] = acc[i];
        }
        __syncthreads();
        if (grp == 0) {
#pragma unroll
            for (int g = 1; g < NGRP; g++) {
                float* rg = dyn + g * GRP2_F;
#pragma unroll
                for (int i = 0; i < NACC; i++) acc[i] += rg[i * 128 + ltid];
            }
#pragma unroll
            for (int j = 0; j < NMMA; j++) {
                int cb = n0 + wc0 + 8 * j + 2 * tg;
                float2 bv = *(const float2*)(bias + cb);
                float2 o0 = make_float2(acc[4 * j] + bv.x, acc[4 * j + 1] + bv.y);
                float2 o1 = make_float2(acc[4 * j + 2] + bv.x, acc[4 * j + 3] + bv.y);
                if (ACT == 1) {
                    o0.x = eluf_(o0.x); o0.y = eluf_(o0.y);
                    o1.x = eluf_(o1.x); o1.y = eluf_(o1.y);
                }
                *(float2*)(C + (size_t)(m0 + gr) * N + cb) = o0;
                *(float2*)(C + (size_t)(m0 + gr + 8) * N + cb) = o1;
            }
        }
        __syncthreads();
    }
}

// ---------------- warp-MMA tf32 LSTM step ----------------------------------------
// CTA tile: 32 batch x 64 gate cols. Virtual K order: [h(512) | x(128)].
// h chunks 0..7 via cp.async (ring of 4); x chunks 8,9 staged from prefetch regs.
__device__ void lstm_mma(int t, const float* __restrict__ x,
                         const float* __restrict__ hin, float* __restrict__ hout,
                         float* Wsm, float* Aring, float* Xbuf,
                         const float* bsum, int m0, int h0,
                         float4& xr0, float4& xr1)
{
    const int tid = threadIdx.x;
    const int wid = tid >> 5, lane = tid & 31;
    const int row = tid >> 4, q = tid & 15;

    // stage x_t from regs (tf32-rounded)
    *(float4*)(Xbuf + row * AS + 4 * q) = tf32r4(xr0);
    *(float4*)(Xbuf + ABUF_FLTS + row * AS + 4 * q) = tf32r4(xr1);

    // pre-issue h chunks 0..2
#pragma unroll
    for (int c = 0; c < 3; c++) {
        cpasync16(smem_u32(Aring + c * ABUF_FLTS + row * AS + 4 * q),
                  hin + (size_t)(m0 + row) * HH + c * 64 + 4 * q);
        cp_commit();
    }
    // prefetch next step's x into regs
    if (t + 1 < TT) {
        const float* xp = x + ((size_t)(m0 + row) * TT + (t + 1)) * DD;
        xr0 = *(const float4*)(xp + 4 * q);
        xr1 = *(const float4*)(xp + 64 + 4 * q);
    }

    float d[8];
#pragma unroll
    for (int i = 0; i < 8; i++) d[i] = 0.f;

    const int crt = wid & 1, cct = wid >> 1;
    const int gr = lane >> 2, tg = lane & 3;
    const int aoff = (crt * 16 + gr) * AS + tg;
    const int boff0 = (cct * 16 + gr) * WS + tg;
    const int boff1 = (cct * 16 + 8 + gr) * WS + tg;

    for (int c = 0; c < 10; c++) {
        if (c <= 5) cp_wait<2>();
        else if (c == 6) cp_wait<1>();
        else if (c == 7) cp_wait<0>();
        __syncthreads();
        if (c <= 4) {
            cpasync16(smem_u32(Aring + ((c + 3) & 3) * ABUF_FLTS + row * AS + 4 * q),
                      hin + (size_t)(m0 + row) * HH + (c + 3) * 64 + 4 * q);
            cp_commit();
        }
        if (wid < 8) {
            const float* Ab = (c < 8) ? (Aring + (c & 3) * ABUF_FLTS)
                                      : (Xbuf + (c - 8) * ABUF_FLTS);
            const float* Wb = Wsm + c * 64;
#pragma unroll
            for (int s = 0; s < 8; s++) {
                const float* ap = Ab + aoff + s * 8;
                uint32_t a0 = __float_as_uint(ap[0]);
                uint32_t a1 = __float_as_uint(ap[8 * AS]);
                uint32_t a2 = __float_as_uint(ap[4]);
                uint32_t a3 = __float_as_uint(ap[8 * AS + 4]);
                const float* bp0 = Wb + boff0 + s * 8;
                mma8(d, a0, a1, a2, a3,
                     __float_as_uint(bp0[0]), __float_as_uint(bp0[4]));
                const float* bp1 = Wb + boff1 + s * 8;
                mma8(d + 4, a0, a1, a2, a3,
                     __float_as_uint(bp1[0]), __float_as_uint(bp1[4]));
            }
        }
    }

    // D -> Gs (overlays Xbuf[0]; compute warps finished reading it at c=8)
    float* Gs = Xbuf;
    if (wid < 8) {
        int r0 = crt * 16 + gr;
        int c0 = cct * 16 + 2 * tg;
        Gs[r0 * AS + c0] = d[0];           Gs[r0 * AS + c0 + 1] = d[1];
        Gs[(r0 + 8) * AS + c0] = d[2];     Gs[(r0 + 8) * AS + c0 + 1] = d[3];
        Gs[r0 * AS + c0 + 8] = d[4];       Gs[r0 * AS + c0 + 9] = d[5];
        Gs[(r0 + 8) * AS + c0 + 8] = d[6]; Gs[(r0 + 8) * AS + c0 + 9] = d[7];
    }
    __syncthreads();

    int rr = tid >> 4, jj = tid & 15;
    float iv = sigmoidf_(Gs[rr * AS + jj] + bsum[jj]);
    float fv = sigmoidf_(Gs[rr * AS + 16 + jj] + bsum[16 + jj]);
    float gv = tanhf(Gs[rr * AS + 32 + jj] + bsum[32 + jj]);
    float ov = sigmoidf_(Gs[rr * AS + 48 + jj] + bsum[48 + jj]);
    int idx = (m0 + rr) * HH + h0 + jj;
    float cn = fv * g_c[idx] + iv * gv;
    g_c[idx] = cn;
    hout[idx] = tf32r(ov * tanhf(cn));
    __syncthreads();
}

// ---------------- mega persistent kernel (single graph node) ----------------------
__global__ __launch_bounds__(NTHR, 1) void mega_kernel(
    const float* __restrict__ x,
    const float* __restrict__ Wih, const float* __restrict__ Whh,
    const float* __restrict__ bih, const float* __restrict__ bhh,
    const float* __restrict__ ow1, const float* __restrict__ ob1,
    const float* __restrict__ ow2, const float* __restrict__ ob2,
    const float* __restrict__ ow3, const float* __restrict__ ob3,
    const float* __restrict__ dw1, const float* __restrict__ db1,
    const float* __restrict__ dw2, const float* __restrict__ db2,
    float* __restrict__ out)
{
    extern __shared__ float dyn[];
    __shared__ float s_bsum[64];

    const int tid = threadIdx.x;
    const int gidx = blockIdx.x * NTHR + tid;
    const int h0 = (blockIdx.x & 31) * 16;
    const int m0 = (blockIdx.x >> 5) * 32;
    const int row = tid >> 4, q = tid & 15;

    g_h[0][gidx] = 0.f;
    g_c[gidx] = 0.f;

    // ---- LSTM setup: resident W, k-order [Whh | Wih], tf32-rounded ----
    float* Wsm = dyn;
    float* Aring = dyn + WSM_FLTS;
    float* Xbuf = dyn + WSM_FLTS + 4 * ABUF_FLTS;
    for (int e = tid; e < 64 * 160; e += NTHR) {
        int c = e / 160, w4 = e % 160;
        int kg = 4 * w4;
        int wr = (c >> 4) * HH + h0 + (c & 15);
        float4 v = (kg < HH) ? *(const float4*)(Whh + (size_t)wr * HH + kg)
                             : *(const float4*)(Wih + (size_t)wr * DD + (kg - HH));
        *(float4*)(Wsm + c * WS + kg) = tf32r4(v);
    }
    if (tid < 64) {
        int wr = (tid >> 4) * HH + h0 + (tid & 15);
        s_bsum[tid] = bih[wr] + bhh[wr];
    }
    // prologue: x(t=0) into regs
    float4 xr0, xr1;
    {
        const float* xp = x + (size_t)(m0 + row) * TT * DD;
        xr0 = *(const float4*)(xp + 4 * q);
        xr1 = *(const float4*)(xp + 64 + 4 * q);
    }
    gsync();

    // ---- LSTM encoder: 1024 steps on HMMA tf32 ----
    for (int t = 0; t < TT; t++) {
        const float* hin = (t & 1) ? g_h[1] : g_h[0];
        float* hout      = (t & 1) ? g_h[0] : g_h[1];
        lstm_mma(t, x, hin, hout, Wsm, Aring, Xbuf, s_bsum, m0, h0, xr0, xr1);
        gsync();
    }

    // ---- z0 = c_n; pred slot 0 ----
    {
        float v = g_c[gidx];
        g_z[gidx] = v;
        int bb = gidx >> 9, hh = gidx & 511;
        g_pred[(bb * 5) * HH + hh] = v;
    }
    gsync();

    // ---- latent ODE: 32 RK4 substeps on MMA tf32 ----
    const double dtd = (5.0 / 60.0) / 8.0;
    const float dtf  = (float)dtd;
    const float half = (float)(0.5 * dtd);
    const float dt6  = (float)(dtd / 6.0);

    for (int step = 0; step < 32; step++) {
        gemm_mma<1, false, 64>(dyn, g_z, nullptr, 0.f, ow1, ob1, g_t1, BB, NHID, HH); gsync();
        gemm_mma<1, false, 64>(dyn, g_t1, nullptr, 0.f, ow2, ob2, g_t2, BB, NHID, NHID); gsync();
        gemm_mma<0, false, 32>(dyn, g_t2, nullptr, 0.f, ow3, ob3, g_k[0], BB, HH, NHID); gsync();

        gemm_mma<1, true, 64>(dyn, g_z, g_k[0], half, ow1, ob1, g_t1, BB, NHID, HH); gsync();
        gemm_mma<1, false, 64>(dyn, g_t1, nullptr, 0.f, ow2, ob2, g_t2, BB, NHID, NHID); gsync();
        gemm_mma<0, false, 32>(dyn, g_t2, nullptr, 0.f, ow3, ob3, g_k[1], BB, HH, NHID); gsync();

        gemm_mma<1, true, 64>(dyn, g_z, g_k[1], half, ow1, ob1, g_t1, BB, NHID, HH); gsync();
        gemm_mma<1, false, 64>(dyn, g_t1, nullptr, 0.f, ow2, ob2, g_t2, BB, NHID, NHID); gsync();
        gemm_mma<0, false, 32>(dyn, g_t2, nullptr, 0.f, ow3, ob3, g_k[2], BB, HH, NHID); gsync();

        gemm_mma<1, true, 64>(dyn, g_z, g_k[2], dtf, ow1, ob1, g_t1, BB, NHID, HH); gsync();
        gemm_mma<1, false, 64>(dyn, g_t1, nullptr, 0.f, ow2, ob2, g_t2, BB, NHID, NHID); gsync();
        gemm_mma<0, false, 32>(dyn, g_t2, nullptr, 0.f, ow3, ob3, g_k[3], BB, HH, NHID); gsync();

        {
            float z = g_z[gidx] + dt6 * (g_k[0][gidx] + 2.f * (g_k[1][gidx] + g_k[2][gidx]) + g_k[3][gidx]);
            g_z[gidx] = z;
            if ((step & 7) == 7) {
                int bb = gidx >> 9, hh = gidx & 511;
                g_pred[(bb * 5 + (step >> 3) + 1) * HH + hh] = z;
            }
        }
        gsync();
    }

    // ---- decoder (fp32 SIMT — preserves precision budget) ----
    gemm_simt<2>(dyn, g_pred, dw1, db1, g_dec1, BB * 5, NHID, HH);
    gsync();
    gemm_simt<0>(dyn, g_dec1, dw2, db2, out, BB * 5, DD, NHID);
}

// ---------------- host side --------------------------------------------------------
extern "C" void kernel_launch(void* const* d_in, const int* in_sizes, int n_in,
                              void* d_out, int out_size)
{
    const float* inputs = (const float*)d_in[0];

    int p = 2;
    for (int i = 1; i + 1 < n_in; i++) {
        if (in_sizes[i] == 4 * HH * DD && in_sizes[i + 1] == 4 * HH * HH) { p = i; break; }
    }
    const float* W_ih = (const float*)d_in[p + 0];
    const float* W_hh = (const float*)d_in[p + 1];
    const float* b_ih = (const float*)d_in[p + 2];
    const float* b_hh = (const float*)d_in[p + 3];
    const float* ow1 = (const float*)d_in[p + 4];
    const float* ob1 = (const float*)d_in[p + 5];
    const float* ow2 = (const float*)d_in[p + 6];
    const float* ob2 = (const float*)d_in[p + 7];
    const float* ow3 = (const float*)d_in[p + 8];
    const float* ob3 = (const float*)d_in[p + 9];
    const float* dw1 = (const float*)d_in[p + 10];
    const float* db1 = (const float*)d_in[p + 11];
    const float* dw2 = (const float*)d_in[p + 12];
    const float* db2 = (const float*)d_in[p + 13];

    cudaFuncSetAttribute(mega_kernel, cudaFuncAttributeMaxDynamicSharedMemorySize,
                         DYN_BYTES);

    mega_kernel<<<GRID, NTHR, DYN_BYTES>>>(inputs, W_ih, W_hh, b_ih, b_hh,
                                           ow1, ob1, ow2, ob2, ow3, ob3,
                                           dw1, db1, dw2, db2, (float*)d_out);
}

// round 14
// speedup vs baseline: 2.9756x; 1.0250x over previous
#include <cuda_runtime.h>
#include <math.h>
#include <stdint.h>

#define BB   128
#define TT   1024
#define DD   128
#define HH   512
#define NHID 1024
#define GRID 128
#define NTHR 512
#define NGRP 4

typedef unsigned long long ull;

// ---- SIMT (decoder) smem layout ----
#define A_BUF 1024
#define W_BUF 2048
#define GRP_F (2 * A_BUF + 2 * W_BUF)
// ---- ODE MMA smem layout: per group 2x(16x36) A + 2x(64x36) W ----
#define AS2 36
#define GRP2_F (2 * 16 * AS2 + 2 * 64 * AS2)   /* 5760 floats */
// ---- LSTM MMA smem: W resident 64x648 + 4 h-ring (32x72) + 2 x-buf (32x72) ----
#define WS   648
#define AS   72
#define ABUF_FLTS (32 * AS)                    /* 2304 */
#define WSM_FLTS  (64 * WS)                    /* 41472 */
#define LSTM_FLTS (WSM_FLTS + 6 * ABUF_FLTS)   /* 55296 */
#define DYN_BYTES (LSTM_FLTS * 4)              /* 221184 */

__device__ float g_h[2][BB * HH];
__device__ float g_c[BB * HH];
__device__ float g_z[BB * HH];
__device__ float g_k[4][BB * HH];
__device__ float g_t1[BB * NHID];
__device__ float g_t2[BB * NHID];
__device__ float g_pred[BB * 5 * HH];
__device__ float g_dec1[BB * 5 * NHID];

__device__ unsigned g_cnt = 0;
__device__ volatile unsigned g_gen = 0;
__device__ unsigned g_gcnt[4 * 32];            // stride 32 to separate L2 lines
__device__ volatile unsigned g_ggen[4 * 32];

// ---------------- grid barrier (full, CG-style 1-thread fence) -----------------
__device__ __forceinline__ void gsync() {
    __syncthreads();
    if (threadIdx.x == 0) {
        unsigned gen = g_gen;
        asm volatile("fence.acq_rel.gpu;" ::: "memory");
        if (atomicAdd(&g_cnt, 1u) == gen * GRID + (GRID - 1)) {
            g_gen = gen + 1;
        } else {
            while (g_gen == gen) { }
        }
        asm volatile("fence.acq_rel.gpu;" ::: "memory");
    }
    __syncthreads();
}
// ---------------- group barrier: 32 CTAs sharing one m-tile --------------------
__device__ __forceinline__ void gsync_grp(int g) {
    __syncthreads();
    if (threadIdx.x == 0) {
        unsigned gen = g_ggen[g * 32];
        asm volatile("fence.acq_rel.gpu;" ::: "memory");
        if (atomicAdd(&g_gcnt[g * 32], 1u) == gen * 32u + 31u) {
            g_ggen[g * 32] = gen + 1;
        } else {
            while (g_ggen[g * 32] == gen) { }
        }
        asm volatile("fence.acq_rel.gpu;" ::: "memory");
    }
    __syncthreads();
}

// ---------------- packed f32x2 helpers (decoder SIMT path) ---------------------
__device__ __forceinline__ void fma2(ull& acc, ull a, ull b) {
    asm("fma.rn.f32x2 %0, %1, %2, %0;" : "+l"(acc) : "l"(a), "l"(b));
}
__device__ __forceinline__ ull addf2(ull a, ull b) {
    ull r; asm("add.rn.f32x2 %0, %1, %2;" : "=l"(r) : "l"(a), "l"(b)); return r;
}
__device__ __forceinline__ ull pack2(float x) {
    ull r; asm("mov.b64 %0, {%1, %1};" : "=l"(r) : "f"(x)); return r;
}
__device__ __forceinline__ float2 unpack2(ull v) {
    float2 r; asm("mov.b64 {%0, %1}, %2;" : "=f"(r.x), "=f"(r.y) : "l"(v)); return r;
}
__device__ __forceinline__ float sigmoidf_(float x) { return 1.f / (1.f + expf(-x)); }
__device__ __forceinline__ float eluf_(float x)     { return x > 0.f ? x : expm1f(x); }

__device__ __forceinline__ void gbar(int grp) {
    asm volatile("bar.sync %0, 128;" :: "r"(grp + 1) : "memory");
}

// ---------------- async-copy / tf32 / mma helpers ------------------------------
__device__ __forceinline__ uint32_t smem_u32(const void* p) {
    uint32_t a;
    asm("{ .reg .u64 t; cvta.to.shared.u64 t, %1; cvt.u32.u64 %0, t; }" : "=r"(a) : "l"(p));
    return a;
}
__device__ __forceinline__ void cpasync16(uint32_t dst, const void* src) {
    asm volatile("cp.async.cg.shared.global [%0], [%1], 16;" :: "r"(dst), "l"(src));
}
__device__ __forceinline__ void cp_commit() {
    asm volatile("cp.async.commit_group;" ::: "memory");
}
template <int N>
__device__ __forceinline__ void cp_wait() {
    asm volatile("cp.async.wait_group %0;" :: "n"(N) : "memory");
}
__device__ __forceinline__ float tf32r(float x) {
    uint32_t r; asm("cvt.rna.tf32.f32 %0, %1;" : "=r"(r) : "f"(x));
    return __uint_as_float(r);
}
__device__ __forceinline__ float4 tf32r4(float4 v) {
    v.x = tf32r(v.x); v.y = tf32r(v.y); v.z = tf32r(v.z); v.w = tf32r(v.w);
    return v;
}
__device__ __forceinline__ void mma8(float* d, uint32_t a0, uint32_t a1,
                                     uint32_t a2, uint32_t a3,
                                     uint32_t b0, uint32_t b1) {
    asm volatile(
        "mma.sync.aligned.m16n8k8.row.col.f32.tf32.tf32.f32 "
        "{%0,%1,%2,%3}, {%4,%5,%6,%7}, {%8,%9}, {%0,%1,%2,%3};"
        : "+f"(d[0]), "+f"(d[1]), "+f"(d[2]), "+f"(d[3])
        : "r"(a0), "r"(a1), "r"(a2), "r"(a3), "r"(b0), "r"(b1));
}
// permute k within its 8-group so (k, k+4) become adjacent words
__device__ __forceinline__ int permk(int k) {
    return (k & ~7) | (((k & 3) << 1) | ((k >> 2) & 1));
}

// ---------------- SIMT GEMM (decoder only) --------------------------------------
__device__ __forceinline__ void stA32(float* Ab, float4 v, int lkq, int r) {
    float* p = Ab + lkq * 4 * 32 + ((((r >> 2) ^ lkq) & 7) << 2) + (r & 3);
    p[0] = v.x; p[32] = v.y; p[64] = v.z; p[96] = v.w;
}
__device__ __forceinline__ void stW64(float* Wb, float4 v, int lkq, int col) {
    float* p = Wb + lkq * 4 * 64 + ((((col >> 2) ^ lkq) & 15) << 2) + (col & 3);
    p[0] = v.x; p[64] = v.y; p[128] = v.z; p[192] = v.w;
}
__device__ __forceinline__ void kfma32(const float* Ab, const float* Wb,
                                       int tx, int ty, ull* acc) {
#pragma unroll
    for (int k = 0; k < 32; k++) {
        const int c = k >> 2;
        float4 a = *(const float4*)&Ab[k * 32 + (((ty ^ c) & 7) << 2)];
        ulonglong2 w = *(const ulonglong2*)&Wb[k * 64 + (((tx ^ c) & 15) << 2)];
        ull ax = pack2(a.x), ay = pack2(a.y), az = pack2(a.z), aw = pack2(a.w);
        fma2(acc[0], ax, w.x); fma2(acc[1], ax, w.y);
        fma2(acc[2], ay, w.x); fma2(acc[3], ay, w.y);
        fma2(acc[4], az, w.x); fma2(acc[5], az, w.y);
        fma2(acc[6], aw, w.x); fma2(acc[7], aw, w.y);
    }
}
template <int ACT>
__device__ void gemm_simt(float* dyn, const float* __restrict__ A,
                          const float* __restrict__ W, const float* __restrict__ bias,
                          float* __restrict__ C, int M, int N, int K)
{
    const int tid = threadIdx.x;
    const int grp = tid >> 7, ltid = tid & 127;
    const int tx = ltid & 15, ty = ltid >> 4;
    const int lr = ltid >> 3, lkq = ltid & 7;
    float* gd = dyn + grp * GRP_F;
    const int kgrp = K >> 2, nkb = kgrp >> 5;
    const int koff0 = grp * kgrp + lkq * 4;
    const int ntiles = N >> 6;
    const int total = ntiles * (M >> 5);

    for (int tile = blockIdx.x; tile < total; tile += GRID) {
        int n0 = (tile % ntiles) << 6;
        int m0 = (tile / ntiles) << 5;

        ull acc[8];
#pragma unroll
        for (int i = 0; i < 8; i++) acc[i] = 0;

        float4 av[2], wv[4];
#pragma unroll
        for (int j = 0; j < 2; j++)
            av[j] = *(const float4*)(A + (size_t)(m0 + lr + 16 * j) * K + koff0);
#pragma unroll
        for (int j = 0; j < 4; j++)
            wv[j] = *(const float4*)(W + (size_t)(n0 + lr + 16 * j) * K + koff0);

        for (int kb = 0; kb < nkb; kb++) {
            float* Ab = gd + (kb & 1) * A_BUF;
            float* Wb = gd + 2 * A_BUF + (kb & 1) * W_BUF;
#pragma unroll
            for (int j = 0; j < 2; j++) stA32(Ab, av[j], lkq, lr + 16 * j);
#pragma unroll
            for (int j = 0; j < 4; j++) stW64(Wb, wv[j], lkq, lr + 16 * j);
            gbar(grp);
            if (kb + 1 < nkb) {
                int ko = koff0 + (kb + 1) * 32;
#pragma unroll
                for (int j = 0; j < 2; j++)
                    av[j] = *(const float4*)(A + (size_t)(m0 + lr + 16 * j) * K + ko);
#pragma unroll
                for (int j = 0; j < 4; j++)
                    wv[j] = *(const float4*)(W + (size_t)(n0 + lr + 16 * j) * K + ko);
            }
            kfma32(Ab, Wb, tx, ty, acc);
        }

        __syncthreads();
        if (grp > 0) {
            ull* rg = (ull*)(dyn + grp * GRP_F);
#pragma unroll
            for (int i = 0; i < 8; i++) rg[i * 128 + ltid] = acc[i];
        }
        __syncthreads();
        if (grp == 0) {
#pragma unroll
            for (int g = 1; g < NGRP; g++) {
                ull* rg = (ull*)(dyn + g * GRP_F);
#pragma unroll
                for (int i = 0; i < 8; i++) acc[i] = addf2(acc[i], rg[i * 128 + ltid]);
            }
            float4 bv = *(const float4*)(bias + n0 + 4 * tx);
#pragma unroll
            for (int r = 0; r < 4; r++) {
                int row = m0 + 4 * ty + r;
                float2 lo = unpack2(acc[r * 2]), hi = unpack2(acc[r * 2 + 1]);
                float4 o = make_float4(lo.x + bv.x, lo.y + bv.y, hi.x + bv.z, hi.y + bv.w);
                if (ACT == 2) {
                    o.x = fmaxf(o.x, 0.f); o.y = fmaxf(o.y, 0.f);
                    o.z = fmaxf(o.z, 0.f); o.w = fmaxf(o.w, 0.f);
                }
                *(float4*)(C + (size_t)row * N + n0 + 4 * tx) = o;
            }
        }
        __syncthreads();
    }
}

// ---------------- MMA GEMM for ODE: C[M,N] = act(tf32(Aeff) @ tf32(W)^T + b) -----
// CTA tile 16 x BN, split-K x4 (4 groups x 4 warps), warp tile 16 x (BN/4).
// Single gbar per kblock (double-buffered; trailing bar proven redundant).
template <int ACT, bool HASA2, int BN>
__device__ void gemm_mma(float* dyn, const float* __restrict__ A,
                         const float* __restrict__ A2, float alpha,
                         const float* __restrict__ W, const float* __restrict__ bias,
                         float* __restrict__ C, int M, int N, int K)
{
    constexpr int NMMA = BN / 32;
    constexpr int NACC = 4 * NMMA;
    constexpr int WN4  = BN / 16;

    const int tid = threadIdx.x;
    const int grp = tid >> 7, ltid = tid & 127;
    const int w = ltid >> 5, lane = tid & 31;
    const int gr = lane >> 2, tg = lane & 3;
    float* gd = dyn + grp * GRP2_F;
    float* Ab0 = gd;
    float* Wb0 = gd + 2 * 16 * AS2;
    const int kgrp = K >> 2, nkb = kgrp >> 5;
    const int koff = grp * kgrp;
    const int ntiles = N / BN;
    const int total = ntiles * (M >> 4);
    const int ar = ltid >> 3, aseg = ltid & 7;
    const int wc0 = w * (BN / 4);

    for (int tile = blockIdx.x; tile < total; tile += GRID) {
        int n0 = (tile % ntiles) * BN;
        int m0 = (tile / ntiles) << 4;

        float acc[NACC];
#pragma unroll
        for (int i = 0; i < NACC; i++) acc[i] = 0.f;

        float4 avr;
        float4 wvr[WN4];
        {
            float4 v = *(const float4*)(A + (size_t)(m0 + ar) * K + koff + 4 * aseg);
            if (HASA2) {
                float4 v2 = *(const float4*)(A2 + (size_t)(m0 + ar) * K + koff + 4 * aseg);
                v.x = fmaf(alpha, v2.x, v.x); v.y = fmaf(alpha, v2.y, v.y);
                v.z = fmaf(alpha, v2.z, v.z); v.w = fmaf(alpha, v2.w, v.w);
            }
            avr = tf32r4(v);
#pragma unroll
            for (int i = 0; i < WN4; i++) {
                int flat = ltid + 128 * i;
                int wc = flat >> 3, wseg = flat & 7;
                wvr[i] = tf32r4(*(const float4*)(W + (size_t)(n0 + wc) * K + koff + 4 * wseg));
            }
        }

        for (int kb = 0; kb < nkb; kb++) {
            float* Ab = Ab0 + (kb & 1) * 16 * AS2;
            float* Wb = Wb0 + (kb & 1) * 64 * AS2;
            *(float4*)(Ab + ar * AS2 + 4 * aseg) = avr;
#pragma unroll
            for (int i = 0; i < WN4; i++) {
                int flat = ltid + 128 * i;
                int wc = flat >> 3, wseg = flat & 7;
                *(float4*)(Wb + wc * AS2 + 4 * wseg) = wvr[i];
            }
            gbar(grp);
            if (kb + 1 < nkb) {
                int ko = koff + (kb + 1) * 32;
                float4 v = *(const float4*)(A + (size_t)(m0 + ar) * K + ko + 4 * aseg);
                if (HASA2) {
                    float4 v2 = *(const float4*)(A2 + (size_t)(m0 + ar) * K + ko + 4 * aseg);
                    v.x = fmaf(alpha, v2.x, v.x); v.y = fmaf(alpha, v2.y, v.y);
                    v.z = fmaf(alpha, v2.z, v.z); v.w = fmaf(alpha, v2.w, v.w);
                }
                avr = tf32r4(v);
#pragma unroll
                for (int i = 0; i < WN4; i++) {
                    int flat = ltid + 128 * i;
                    int wc = flat >> 3, wseg = flat & 7;
                    wvr[i] = tf32r4(*(const float4*)(W + (size_t)(n0 + wc) * K + ko + 4 * wseg));
                }
            }
#pragma unroll
            for (int s = 0; s < 4; s++) {
                const float* ap = Ab + gr * AS2 + s * 8 + tg;
                uint32_t a0 = __float_as_uint(ap[0]);
                uint32_t a1 = __float_as_uint(ap[8 * AS2]);
                uint32_t a2 = __float_as_uint(ap[4]);
                uint32_t a3 = __float_as_uint(ap[8 * AS2 + 4]);
#pragma unroll
                for (int j = 0; j < NMMA; j++) {
                    const float* bp = Wb + (wc0 + 8 * j + gr) * AS2 + s * 8 + tg;
                    uint32_t b0 = __float_as_uint(bp[0]);
                    uint32_t b1 = __float_as_uint(bp[4]);
                    mma8(acc + 4 * j, a0, a1, a2, a3, b0, b1);
                }
            }
        }

        __syncthreads();
        if (grp > 0) {
            float* rg = dyn + grp * GRP2_F;
#pragma unroll
            for (int i = 0; i < NACC; i++) rg[i * 128 + ltid] = acc[i];
        }
        __syncthreads();
        if (grp == 0) {
#pragma unroll
            for (int g = 1; g < NGRP; g++) {
                float* rg = dyn + g * GRP2_F;
#pragma unroll
                for (int i = 0; i < NACC; i++) acc[i] += rg[i * 128 + ltid];
            }
#pragma unroll
            for (int j = 0; j < NMMA; j++) {
                int cb = n0 + wc0 + 8 * j + 2 * tg;
                float2 bv = *(const float2*)(bias + cb);
                float2 o0 = make_float2(acc[4 * j] + bv.x, acc[4 * j + 1] + bv.y);
                float2 o1 = make_float2(acc[4 * j + 2] + bv.x, acc[4 * j + 3] + bv.y);
                if (ACT == 1) {
                    o0.x = eluf_(o0.x); o0.y = eluf_(o0.y);
                    o1.x = eluf_(o1.x); o1.y = eluf_(o1.y);
                }
                *(float2*)(C + (size_t)(m0 + gr) * N + cb) = o0;
                *(float2*)(C + (size_t)(m0 + gr + 8) * N + cb) = o1;
            }
        }
        __syncthreads();
    }
}

// ---------------- warp-MMA tf32 LSTM step ----------------------------------------
// CTA tile: 32 batch x 64 gate cols. Virtual K order: [h(512) | x(128)], k
// PERMUTED within 8-groups so fragment pairs (k, k+4) are word-adjacent -> LDS.64.
__device__ void lstm_mma(int t, const float* __restrict__ x,
                         const float* __restrict__ hin, float* __restrict__ hout,
                         float* Wsm, float* Aring, float* Xbuf,
                         const float* bsum, int m0, int h0,
                         float4& xr0, float4& xr1)
{
    const int tid = threadIdx.x;
    const int wid = tid >> 5, lane = tid & 31;
    const int row = tid >> 4, q = tid & 15;

    // stage x_t from regs (tf32-rounded, k-permuted scalar stores)
    {
        float4 v0 = tf32r4(xr0), v1 = tf32r4(xr1);
        float* xb0 = Xbuf + row * AS;
        float* xb1 = Xbuf + ABUF_FLTS + row * AS;
        int base = 8 * (q >> 1) + (q & 1);   // pos = base + 2*j
        xb0[base + 0] = v0.x; xb0[base + 2] = v0.y;
        xb0[base + 4] = v0.z; xb0[base + 6] = v0.w;
        xb1[base + 0] = v1.x; xb1[base + 2] = v1.y;
        xb1[base + 4] = v1.z; xb1[base + 6] = v1.w;
    }

    // pre-issue h chunks 0..2 (h is stored permuted in global)
#pragma unroll
    for (int c = 0; c < 3; c++) {
        cpasync16(smem_u32(Aring + c * ABUF_FLTS + row * AS + 4 * q),
                  hin + (size_t)(m0 + row) * HH + c * 64 + 4 * q);
        cp_commit();
    }
    // prefetch next step's x into regs
    if (t + 1 < TT) {
        const float* xp = x + ((size_t)(m0 + row) * TT + (t + 1)) * DD;
        xr0 = *(const float4*)(xp + 4 * q);
        xr1 = *(const float4*)(xp + 64 + 4 * q);
    }

    float d[8];
#pragma unroll
    for (int i = 0; i < 8; i++) d[i] = 0.f;

    const int crt = wid & 1, cct = wid >> 1;
    const int gr = lane >> 2, tg = lane & 3;
    const int aoff = (crt * 16 + gr) * AS + 2 * tg;
    const int boff0 = (cct * 16 + gr) * WS + 2 * tg;
    const int boff1 = (cct * 16 + 8 + gr) * WS + 2 * tg;

    for (int c = 0; c < 10; c++) {
        if (c <= 5) cp_wait<2>();
        else if (c == 6) cp_wait<1>();
        else if (c == 7) cp_wait<0>();
        __syncthreads();
        if (c <= 4) {
            cpasync16(smem_u32(Aring + ((c + 3) & 3) * ABUF_FLTS + row * AS + 4 * q),
                      hin + (size_t)(m0 + row) * HH + (c + 3) * 64 + 4 * q);
            cp_commit();
        }
        if (wid < 8) {
            const float* Ab = (c < 8) ? (Aring + (c & 3) * ABUF_FLTS)
                                      : (Xbuf + (c - 8) * ABUF_FLTS);
            const float* Wb = Wsm + c * 64;
#pragma unroll
            for (int s = 0; s < 8; s++) {
                float2 alo = *(const float2*)(Ab + aoff + s * 8);            // (a0,a2)
                float2 ahi = *(const float2*)(Ab + aoff + 8 * AS + s * 8);   // (a1,a3)
                float2 bv0 = *(const float2*)(Wb + boff0 + s * 8);           // (b0,b1)
                float2 bv1 = *(const float2*)(Wb + boff1 + s * 8);
                mma8(d, __float_as_uint(alo.x), __float_as_uint(ahi.x),
                        __float_as_uint(alo.y), __float_as_uint(ahi.y),
                        __float_as_uint(bv0.x), __float_as_uint(bv0.y));
                mma8(d + 4, __float_as_uint(alo.x), __float_as_uint(ahi.x),
                            __float_as_uint(alo.y), __float_as_uint(ahi.y),
                            __float_as_uint(bv1.x), __float_as_uint(bv1.y));
            }
        }
    }

    // D -> Gs (overlays Xbuf[0]; all warps synced at top of c=9 iteration)
    float* Gs = Xbuf;
    if (wid < 8) {
        int r0 = crt * 16 + gr;
        int c0 = cct * 16 + 2 * tg;
        Gs[r0 * AS + c0] = d[0];           Gs[r0 * AS + c0 + 1] = d[1];
        Gs[(r0 + 8) * AS + c0] = d[2];     Gs[(r0 + 8) * AS + c0 + 1] = d[3];
        Gs[r0 * AS + c0 + 8] = d[4];       Gs[r0 * AS + c0 + 9] = d[5];
        Gs[(r0 + 8) * AS + c0 + 8] = d[6]; Gs[(r0 + 8) * AS + c0 + 9] = d[7];
    }
    __syncthreads();

    int rr = tid >> 4, jj = tid & 15;
    float iv = sigmoidf_(Gs[rr * AS + jj] + bsum[jj]);
    float fv = sigmoidf_(Gs[rr * AS + 16 + jj] + bsum[16 + jj]);
    float gv = tanhf(Gs[rr * AS + 32 + jj] + bsum[32 + jj]);
    float ov = sigmoidf_(Gs[rr * AS + 48 + jj] + bsum[48 + jj]);
    int cidx = (m0 + rr) * HH + h0 + jj;
    float cn = fv * g_c[cidx] + iv * gv;
    g_c[cidx] = cn;
    // store h tf32-rounded at the k-PERMUTED position (h consumed only as MMA A)
    int hidx = (m0 + rr) * HH + h0 + (jj & 8) + ((jj & 3) << 1) + ((jj >> 2) & 1);
    hout[hidx] = tf32r(ov * tanhf(cn));
    __syncthreads();
}

// ---------------- mega persistent kernel (single graph node) ----------------------
__global__ __launch_bounds__(NTHR, 1) void mega_kernel(
    const float* __restrict__ x,
    const float* __restrict__ Wih, const float* __restrict__ Whh,
    const float* __restrict__ bih, const float* __restrict__ bhh,
    const float* __restrict__ ow1, const float* __restrict__ ob1,
    const float* __restrict__ ow2, const float* __restrict__ ob2,
    const float* __restrict__ ow3, const float* __restrict__ ob3,
    const float* __restrict__ dw1, const float* __restrict__ db1,
    const float* __restrict__ dw2, const float* __restrict__ db2,
    float* __restrict__ out)
{
    extern __shared__ float dyn[];
    __shared__ float s_bsum[64];

    const int tid = threadIdx.x;
    const int gidx = blockIdx.x * NTHR + tid;
    const int h0 = (blockIdx.x & 31) * 16;
    const int m0 = (blockIdx.x >> 5) * 32;
    const int mgrp = blockIdx.x >> 5;          // m-tile group (32 CTAs each)
    const int row = tid >> 4, q = tid & 15;

    g_h[0][gidx] = 0.f;
    g_c[gidx] = 0.f;

    // ---- LSTM setup: resident W, virtual-k order [Whh | Wih], k-permuted, tf32 ----
    float* Wsm = dyn;
    float* Aring = dyn + WSM_FLTS;
    float* Xbuf = dyn + WSM_FLTS + 4 * ABUF_FLTS;
    for (int e = tid; e < 64 * 160; e += NTHR) {
        int c = e / 160, w4 = e % 160;
        int kg = 4 * w4;
        int wr = (c >> 4) * HH + h0 + (c & 15);
        float4 v = (kg < HH) ? *(const float4*)(Whh + (size_t)wr * HH + kg)
                             : *(const float4*)(Wih + (size_t)wr * DD + (kg - HH));
        v = tf32r4(v);
        float* wp = Wsm + c * WS + (kg & ~7) + (w4 & 1);  // pos = base + 2*j
        wp[0] = v.x; wp[2] = v.y; wp[4] = v.z; wp[6] = v.w;
    }
    if (tid < 64) {
        int wr = (tid >> 4) * HH + h0 + (tid & 15);
        s_bsum[tid] = bih[wr] + bhh[wr];
    }
    // prologue: x(t=0) into regs
    float4 xr0, xr1;
    {
        const float* xp = x + (size_t)(m0 + row) * TT * DD;
        xr0 = *(const float4*)(xp + 4 * q);
        xr1 = *(const float4*)(xp + 64 + 4 * q);
    }
    gsync();

    // ---- LSTM encoder: 1024 steps, per-m-tile group barriers ----
    for (int t = 0; t < TT; t++) {
        const float* hin = (t & 1) ? g_h[1] : g_h[0];
        float* hout      = (t & 1) ? g_h[0] : g_h[1];
        lstm_mma(t, x, hin, hout, Wsm, Aring, Xbuf, s_bsum, m0, h0, xr0, xr1);
        gsync_grp(mgrp);
    }

    // ---- z0 = c_n; pred slot 0 ----
    {
        float v = g_c[gidx];
        g_z[gidx] = v;
        int bb = gidx >> 9, hh = gidx & 511;
        g_pred[(bb * 5) * HH + hh] = v;
    }
    gsync();

    // ---- latent ODE: 32 RK4 substeps on MMA tf32 ----
    const double dtd = (5.0 / 60.0) / 8.0;
    const float dtf  = (float)dtd;
    const float half = (float)(0.5 * dtd);
    const float dt6  = (float)(dtd / 6.0);

    for (int step = 0; step < 32; step++) {
        gemm_mma<1, false, 64>(dyn, g_z, nullptr, 0.f, ow1, ob1, g_t1, BB, NHID, HH); gsync();
        gemm_mma<1, false, 64>(dyn, g_t1, nullptr, 0.f, ow2, ob2, g_t2, BB, NHID, NHID); gsync();
        gemm_mma<0, false, 32>(dyn, g_t2, nullptr, 0.f, ow3, ob3, g_k[0], BB, HH, NHID); gsync();

        gemm_mma<1, true, 64>(dyn, g_z, g_k[0], half, ow1, ob1, g_t1, BB, NHID, HH); gsync();
        gemm_mma<1, false, 64>(dyn, g_t1, nullptr, 0.f, ow2, ob2, g_t2, BB, NHID, NHID); gsync();
        gemm_mma<0, false, 32>(dyn, g_t2, nullptr, 0.f, ow3, ob3, g_k[1], BB, HH, NHID); gsync();

        gemm_mma<1, true, 64>(dyn, g_z, g_k[1], half, ow1, ob1, g_t1, BB, NHID, HH); gsync();
        gemm_mma<1, false, 64>(dyn, g_t1, nullptr, 0.f, ow2, ob2, g_t2, BB, NHID, NHID); gsync();
        gemm_mma<0, false, 32>(dyn, g_t2, nullptr, 0.f, ow3, ob3, g_k[2], BB, HH, NHID); gsync();

        gemm_mma<1, true, 64>(dyn, g_z, g_k[2], dtf, ow1, ob1, g_t1, BB, NHID, HH); gsync();
        gemm_mma<1, false, 64>(dyn, g_t1, nullptr, 0.f, ow2, ob2, g_t2, BB, NHID, NHID); gsync();
        gemm_mma<0, false, 32>(dyn, g_t2, nullptr, 0.f, ow3, ob3, g_k[3], BB, HH, NHID); gsync();

        {
            float z = g_z[gidx] + dt6 * (g_k[0][gidx] + 2.f * (g_k[1][gidx] + g_k[2][gidx]) + g_k[3][gidx]);
            g_z[gidx] = z;
            if ((step & 7) == 7) {
                int bb = gidx >> 9, hh = gidx & 511;
                g_pred[(bb * 5 + (step >> 3) + 1) * HH + hh] = z;
            }
        }
        gsync();
    }

    // ---- decoder (fp32 SIMT — preserves precision budget) ----
    gemm_simt<2>(dyn, g_pred, dw1, db1, g_dec1, BB * 5, NHID, HH);
    gsync();
    gemm_simt<0>(dyn, g_dec1, dw2, db2, out, BB * 5, DD, NHID);
}

// ---------------- host side --------------------------------------------------------
extern "C" void kernel_launch(void* const* d_in, const int* in_sizes, int n_in,
                              void* d_out, int out_size)
{
    const float* inputs = (const float*)d_in[0];

    int p = 2;
    for (int i = 1; i + 1 < n_in; i++) {
        if (in_sizes[i] == 4 * HH * DD && in_sizes[i + 1] == 4 * HH * HH) { p = i; break; }
    }
    const float* W_ih = (const float*)d_in[p + 0];
    const float* W_hh = (const float*)d_in[p + 1];
    const float* b_ih = (const float*)d_in[p + 2];
    const float* b_hh = (const float*)d_in[p + 3];
    const float* ow1 = (const float*)d_in[p + 4];
    const float* ob1 = (const float*)d_in[p + 5];
    const float* ow2 = (const float*)d_in[p + 6];
    const float* ob2 = (const float*)d_in[p + 7];
    const float* ow3 = (const float*)d_in[p + 8];
    const float* ob3 = (const float*)d_in[p + 9];
    const float* dw1 = (const float*)d_in[p + 10];
    const float* db1 = (const float*)d_in[p + 11];
    const float* dw2 = (const float*)d_in[p + 12];
    const float* db2 = (const float*)d_in[p + 13];

    cudaFuncSetAttribute(mega_kernel, cudaFuncAttributeMaxDynamicSharedMemorySize,
                         DYN_BYTES);

    mega_kernel<<<GRID, NTHR, DYN_BYTES>>>(inputs, W_ih, W_hh, b_ih, b_hh,
                                           ow1, ob1, ow2, ob2, ow3, ob3,
                                           dw1, db1, dw2, db2, (float*)d_out);
}